// round 11
// baseline (speedup 1.0000x reference)
#include <cuda_runtime.h>
#include <math.h>

#define SS 512
#define PP 64
#define TT 8
#define NN (SS*PP)            // 32768

#define ENC_ELEMS (NN*72)     // 2359296
#define SEQ_ELEMS (TT*NN*32)  // 8388608

#define AST 68                // padded attention row stride (floats)

typedef unsigned long long u64;

__device__ float g_graph_in[SEQ_ELEMS];        // GAT output -> graph LSTM input
__device__ float g_x2[(size_t)SS*TT*64*64];    // GAT layer0 output (elu'd)
__device__ float g_traj_fb[SEQ_ELEMS];
__device__ float g_graph_fb[SEQ_ELEMS];

__device__ __forceinline__ float tanh_fast(float x){
    float y; asm("tanh.approx.f32 %0, %1;" : "=f"(y) : "f"(x)); return y;
}
__device__ __forceinline__ float sig_fast(float x){
    return 0.5f * tanh_fast(0.5f * x) + 0.5f;
}
__device__ __forceinline__ void fma4(float4& a, float s, const float4 w){
    a.x += s*w.x; a.y += s*w.y; a.z += s*w.z; a.w += s*w.w;
}

#define FMA2(d, a, b) asm("fma.rn.f32x2 %0, %1, %2, %0;" : "+l"(d) : "l"(a), "l"(b))
#define PACK2(d, lo, hi) asm("mov.b64 %0, {%1, %2};" : "=l"(d) : "f"(lo), "f"(hi))
#define UNPACK2(lo, hi, s) asm("mov.b64 {%0, %1}, %2;" : "=f"(lo), "=f"(hi) : "l"(s))

// ---------------------------------------------------------------------------
// LSTM traj: input 3, hidden 32, T=8. Warp = 4 peds (2 f32x2 pairs).
// (unchanged from R10 — measured good)
// ---------------------------------------------------------------------------
__global__ void lstm_traj_kernel(const float* __restrict__ x,
        const float* __restrict__ h0, const float* __restrict__ c0,
        const float* __restrict__ Wih, const float* __restrict__ Whh,
        const float* __restrict__ bih, const float* __restrict__ bhh,
        float* __restrict__ hs)
{
    __shared__ __align__(16) float4 sWhh4[1024];  // [k][lane] -> gates
    __shared__ __align__(16) float4 sWihP[96];    // [j=0..2][lane] -> gates
    __shared__ __align__(16) float4 sb4[32];
    __shared__ __align__(8)  float shhf[1024];    // [w][pp][k][c] pair-interleaved
    const int tid = threadIdx.x;

    for (int i = tid; i < 4096; i += 256) {
        int r = i >> 5, k = i & 31;
        ((float*)sWhh4)[(k*32 + (r & 31))*4 + (r >> 5)] = Whh[i];
    }
    for (int i = tid; i < 384; i += 256) {
        int r = i / 3, j = i - r*3;
        ((float*)sWihP)[(j*32 + (r & 31))*4 + (r >> 5)] = Wih[i];
    }
    if (tid < 128) ((float*)sb4)[(tid & 31)*4 + (tid >> 5)] = bih[tid] + bhh[tid];
    __syncthreads();

    const int lane = tid & 31;
    const int w2 = (tid >> 5) * 2;
    const int n0 = blockIdx.x * 32 + w2 * 2;

    float h[4], c[4];
    #pragma unroll
    for (int r = 0; r < 4; r++) { h[r] = h0[(n0+r)*32 + lane]; c[r] = c0[(n0+r)*32 + lane]; }

    const float4 bb = sb4[lane];
    u64 bd[4];
    PACK2(bd[0], bb.x, bb.x); PACK2(bd[1], bb.y, bb.y);
    PACK2(bd[2], bb.z, bb.z); PACK2(bd[3], bb.w, bb.w);

    const u64* hp0 = (const u64*)shhf + (w2 + 0)*32;
    const u64* hp1 = (const u64*)shhf + (w2 + 1)*32;

    #pragma unroll 1
    for (int t = 0; t < TT; t++) {
        __syncwarp();
        #pragma unroll
        for (int r = 0; r < 4; r++)
            shhf[((w2 + (r>>1))*32 + lane)*2 + (r&1)] = h[r];
        __syncwarp();

        u64 ac[8];
        #pragma unroll
        for (int g = 0; g < 4; g++) { ac[g*2] = bd[g]; ac[g*2+1] = bd[g]; }

        const float* xp = x + ((size_t)t*NN + n0) * 3;
        #pragma unroll
        for (int j = 0; j < 3; j++) {
            float4 wj = sWihP[j*32 + lane];
            u64 xq0, xq1, d0, d1, d2, d3;
            PACK2(xq0, xp[0*3+j], xp[1*3+j]);
            PACK2(xq1, xp[2*3+j], xp[3*3+j]);
            PACK2(d0, wj.x, wj.x); PACK2(d1, wj.y, wj.y);
            PACK2(d2, wj.z, wj.z); PACK2(d3, wj.w, wj.w);
            FMA2(ac[0], xq0, d0); FMA2(ac[1], xq1, d0);
            FMA2(ac[2], xq0, d1); FMA2(ac[3], xq1, d1);
            FMA2(ac[4], xq0, d2); FMA2(ac[5], xq1, d2);
            FMA2(ac[6], xq0, d3); FMA2(ac[7], xq1, d3);
        }

        #pragma unroll
        for (int k = 0; k < 32; k++) {
            float4 wh = sWhh4[k*32 + lane];
            u64 hq0 = hp0[k], hq1 = hp1[k];
            u64 d0, d1, d2, d3;
            PACK2(d0, wh.x, wh.x); PACK2(d1, wh.y, wh.y);
            PACK2(d2, wh.z, wh.z); PACK2(d3, wh.w, wh.w);
            FMA2(ac[0], hq0, d0); FMA2(ac[1], hq1, d0);
            FMA2(ac[2], hq0, d1); FMA2(ac[3], hq1, d1);
            FMA2(ac[4], hq0, d2); FMA2(ac[5], hq1, d2);
            FMA2(ac[6], hq0, d3); FMA2(ac[7], hq1, d3);
        }

        float A[4][4];
        #pragma unroll
        for (int g = 0; g < 4; g++) {
            UNPACK2(A[g][0], A[g][1], ac[g*2]);
            UNPACK2(A[g][2], A[g][3], ac[g*2+1]);
        }
        #pragma unroll
        for (int r = 0; r < 4; r++) {
            c[r] = sig_fast(A[1][r]) * c[r] + sig_fast(A[0][r]) * tanh_fast(A[2][r]);
            h[r] = sig_fast(A[3][r]) * tanh_fast(c[r]);
            hs[((size_t)t*NN + n0 + r)*32 + lane] = h[r];
        }
    }
}

// ---------------------------------------------------------------------------
// GAT layer 0 (unchanged — padded attn)
// ---------------------------------------------------------------------------
__global__ void gat0_kernel(const float* __restrict__ traj,
        const float* __restrict__ w0, const float* __restrict__ as0,
        const float* __restrict__ ad0, const float* __restrict__ b0)
{
    __shared__ __align__(16) float pool[4416];
    __shared__ __align__(16) float shp[4096];
    __shared__ float sS[256], sD[256];
    __shared__ __align__(16) float smean[32], sinv[32];
    __shared__ float srinv[64];
    __shared__ float sas[64], sad[64];
    __shared__ __align__(16) float4 sb0v[4];

    float4* sx4 = (float4*)pool;
    float4* sw4 = (float4*)(pool + 2048);
    const int tid = threadIdx.x;
    const int b = blockIdx.x, sIdx = b >> 3, tIdx = b & 7;

    {
        const float4* src = (const float4*)(traj + ((size_t)tIdx*NN + sIdx*64) * 32);
        for (int i = tid; i < 512; i += 256) sx4[i] = src[i];
        const float4* wsrc = (const float4*)w0;
        for (int i = tid; i < 512; i += 256) sw4[i] = wsrc[i];
        if (tid < 64) { sas[tid] = as0[tid]; sad[tid] = ad0[tid]; }
        if (tid < 4)  sb0v[tid] = ((const float4*)b0)[tid];
    }
    __syncthreads();

    if (tid < 32) {
        const float* xs = pool;
        float s = 0.f, s2 = 0.f;
        for (int p = 0; p < 64; p++) { float v = xs[p*32 + tid]; s += v; s2 += v*v; }
        float m = s * (1.0f/64.0f);
        float var = s2 * (1.0f/64.0f) - m*m;
        smean[tid] = m; sinv[tid] = rsqrtf(var + 1e-5f);
    }
    __syncthreads();
    for (int i = tid; i < 512; i += 256) {
        int f4 = i & 7;
        float4 m4 = ((float4*)smean)[f4], i4 = ((float4*)sinv)[f4];
        float4 v = sx4[i];
        v.x = (v.x - m4.x)*i4.x; v.y = (v.y - m4.y)*i4.y;
        v.z = (v.z - m4.z)*i4.z; v.w = (v.w - m4.w)*i4.w;
        sx4[i] = v;
    }
    __syncthreads();

    for (int it = tid; it < 1024; it += 256) {
        int p = it >> 4, j = it & 15, hh = j >> 2, o4 = j & 3;
        float4 acc = {0.f,0.f,0.f,0.f};
        #pragma unroll
        for (int f4 = 0; f4 < 8; f4++) {
            float4 xv = sx4[p*8 + f4];
            fma4(acc, xv.x, sw4[hh*128 + (f4*4+0)*4 + o4]);
            fma4(acc, xv.y, sw4[hh*128 + (f4*4+1)*4 + o4]);
            fma4(acc, xv.z, sw4[hh*128 + (f4*4+2)*4 + o4]);
            fma4(acc, xv.w, sw4[hh*128 + (f4*4+3)*4 + o4]);
        }
        ((float4*)shp)[p*16 + hh*4 + o4] = acc;
    }
    __syncthreads();

    {
        int hh = tid >> 6, p = tid & 63;
        const float4* hp4 = (const float4*)shp;
        float as = 0.f, ad = 0.f;
        #pragma unroll
        for (int o4 = 0; o4 < 4; o4++) {
            float4 v = hp4[p*16 + hh*4 + o4];
            int ob = hh*16 + o4*4;
            as += v.x*sas[ob] + v.y*sas[ob+1] + v.z*sas[ob+2] + v.w*sas[ob+3];
            ad += v.x*sad[ob] + v.y*sad[ob+1] + v.z*sad[ob+2] + v.w*sad[ob+3];
        }
        sS[tid] = as; sD[tid] = ad;
    }
    __syncthreads();

    float* sattn = pool;

    for (int hh = 0; hh < 4; hh++) {
        {
            int p = tid >> 2, q = tid & 3;
            float sp = sS[hh*64 + p];
            float l[16]; float mx = -1e30f;
            #pragma unroll
            for (int mm = 0; mm < 16; mm++) {
                float v = sp + sD[hh*64 + q*16 + mm];
                v = (v > 0.f) ? v : 0.2f*v;
                l[mm] = v; mx = fmaxf(mx, v);
            }
            mx = fmaxf(mx, __shfl_xor_sync(0xffffffffu, mx, 1));
            mx = fmaxf(mx, __shfl_xor_sync(0xffffffffu, mx, 2));
            float sum = 0.f;
            #pragma unroll
            for (int mm = 0; mm < 16; mm++) {
                float e = __expf(l[mm] - mx);
                sattn[p*AST + q*16 + mm] = e; sum += e;
            }
            sum += __shfl_xor_sync(0xffffffffu, sum, 1);
            sum += __shfl_xor_sync(0xffffffffu, sum, 2);
            if (q == 0) srinv[p] = 1.0f / sum;
        }
        __syncthreads();
        {
            int p = tid >> 2, o4 = tid & 3;
            const float* ap = &sattn[p*AST];
            const float4* hp4 = (const float4*)shp;
            float4 acc = {0.f,0.f,0.f,0.f};
            #pragma unroll
            for (int m = 0; m < 64; m++) fma4(acc, ap[m], hp4[m*16 + hh*4 + o4]);
            float ri = srinv[p];
            float4 bb = sb0v[o4];
            float4 res;
            res.x = acc.x*ri + bb.x; res.y = acc.y*ri + bb.y;
            res.z = acc.z*ri + bb.z; res.w = acc.w*ri + bb.w;
            res.x = (res.x > 0.f) ? res.x : (__expf(res.x) - 1.f);
            res.y = (res.y > 0.f) ? res.y : (__expf(res.y) - 1.f);
            res.z = (res.z > 0.f) ? res.z : (__expf(res.z) - 1.f);
            res.w = (res.w > 0.f) ? res.w : (__expf(res.w) - 1.f);
            ((float4*)g_x2)[((size_t)b*64 + p)*16 + hh*4 + o4] = res;
        }
        __syncthreads();
    }
}

// ---------------------------------------------------------------------------
// GAT layer 1 (unchanged — padded attn)
// ---------------------------------------------------------------------------
__global__ void gat1_kernel(const float* __restrict__ w1, const float* __restrict__ as1,
        const float* __restrict__ ad1, const float* __restrict__ b1)
{
    __shared__ __align__(16) float pool[4416];
    __shared__ __align__(16) float sw[2048];
    __shared__ __align__(16) float shp[2048];
    __shared__ float sS[64], sD[64];
    __shared__ __align__(16) float smean[64], sinv[64];
    __shared__ float srinv[64], sas[32], sad[32];
    __shared__ __align__(16) float4 sb1v[8];

    float4* sx4 = (float4*)pool;
    float4* sw4 = (float4*)sw;
    const int tid = threadIdx.x;
    const int b = blockIdx.x, sIdx = b >> 3, tIdx = b & 7;

    {
        const float4* src = (const float4*)(g_x2 + (size_t)b*4096);
        for (int i = tid; i < 1024; i += 256) sx4[i] = src[i];
        const float4* wsrc = (const float4*)w1;
        for (int i = tid; i < 512; i += 256) sw4[i] = wsrc[i];
        if (tid < 32) { sas[tid] = as1[tid]; sad[tid] = ad1[tid]; }
        if (tid < 8)  sb1v[tid] = ((const float4*)b1)[tid];
    }
    __syncthreads();

    if (tid < 64) {
        float s = 0.f, s2 = 0.f;
        for (int p = 0; p < 64; p++) { float v = pool[p*64 + tid]; s += v; s2 += v*v; }
        float m = s * (1.0f/64.0f);
        float var = s2 * (1.0f/64.0f) - m*m;
        smean[tid] = m; sinv[tid] = rsqrtf(var + 1e-5f);
    }
    __syncthreads();
    for (int i = tid; i < 1024; i += 256) {
        int f4 = i & 15;
        float4 m4 = ((float4*)smean)[f4], i4 = ((float4*)sinv)[f4];
        float4 v = sx4[i];
        v.x = (v.x - m4.x)*i4.x; v.y = (v.y - m4.y)*i4.y;
        v.z = (v.z - m4.z)*i4.z; v.w = (v.w - m4.w)*i4.w;
        sx4[i] = v;
    }
    __syncthreads();

    for (int it = tid; it < 512; it += 256) {
        int p = it >> 3, o4 = it & 7;
        float4 acc = {0.f,0.f,0.f,0.f};
        #pragma unroll
        for (int f4 = 0; f4 < 16; f4++) {
            float4 xv = sx4[p*16 + f4];
            fma4(acc, xv.x, sw4[(f4*4+0)*8 + o4]);
            fma4(acc, xv.y, sw4[(f4*4+1)*8 + o4]);
            fma4(acc, xv.z, sw4[(f4*4+2)*8 + o4]);
            fma4(acc, xv.w, sw4[(f4*4+3)*8 + o4]);
        }
        ((float4*)shp)[p*8 + o4] = acc;
    }
    __syncthreads();

    if (tid < 64) {
        int p = tid;
        const float4* hp4 = (const float4*)shp;
        float as = 0.f, ad = 0.f;
        #pragma unroll
        for (int o4 = 0; o4 < 8; o4++) {
            float4 v = hp4[p*8 + o4];
            as += v.x*sas[o4*4] + v.y*sas[o4*4+1] + v.z*sas[o4*4+2] + v.w*sas[o4*4+3];
            ad += v.x*sad[o4*4] + v.y*sad[o4*4+1] + v.z*sad[o4*4+2] + v.w*sad[o4*4+3];
        }
        sS[p] = as; sD[p] = ad;
    }
    __syncthreads();

    float* sattn = pool;
    {
        int p = tid >> 2, q = tid & 3;
        float sp = sS[p];
        float l[16]; float mx = -1e30f;
        #pragma unroll
        for (int mm = 0; mm < 16; mm++) {
            float v = sp + sD[q*16 + mm];
            v = (v > 0.f) ? v : 0.2f*v;
            l[mm] = v; mx = fmaxf(mx, v);
        }
        mx = fmaxf(mx, __shfl_xor_sync(0xffffffffu, mx, 1));
        mx = fmaxf(mx, __shfl_xor_sync(0xffffffffu, mx, 2));
        float sum = 0.f;
        #pragma unroll
        for (int mm = 0; mm < 16; mm++) {
            float e = __expf(l[mm] - mx);
            sattn[p*AST + q*16 + mm] = e; sum += e;
        }
        sum += __shfl_xor_sync(0xffffffffu, sum, 1);
        sum += __shfl_xor_sync(0xffffffffu, sum, 2);
        if (q == 0) srinv[p] = 1.0f / sum;
    }
    __syncthreads();

    for (int it = tid; it < 512; it += 256) {
        int p = it >> 3, o4 = it & 7;
        const float* ap = &sattn[p*AST];
        const float4* hp4 = (const float4*)shp;
        float4 acc = {0.f,0.f,0.f,0.f};
        #pragma unroll
        for (int m = 0; m < 64; m++) fma4(acc, ap[m], hp4[m*8 + o4]);
        float ri = srinv[p];
        float4 bb = sb1v[o4];
        float4 res;
        res.x = acc.x*ri + bb.x; res.y = acc.y*ri + bb.y;
        res.z = acc.z*ri + bb.z; res.w = acc.w*ri + bb.w;
        ((float4*)g_graph_in)[((size_t)tIdx*NN + sIdx*64 + p)*8 + o4] = res;
    }
}

// ---------------------------------------------------------------------------
// LSTM graph (fused x+h): input 32, hidden 32. Warp = 8 peds (4 f32x2 pairs).
// Weight LDS amortized over 8 peds; x/h via u64-pair broadcast LDS.128.
// ---------------------------------------------------------------------------
__global__ void lstm_graph_kernel(
        const float* __restrict__ h0, const float* __restrict__ c0,
        const float* __restrict__ Wih, const float* __restrict__ Whh,
        const float* __restrict__ bih, const float* __restrict__ bhh,
        float* __restrict__ hs)
{
    __shared__ __align__(16) float4 sWih4[1024];  // [k][lane] -> gates
    __shared__ __align__(16) float4 sWhh4[1024];
    __shared__ __align__(16) float4 sb4[32];
    __shared__ __align__(16) u64 shx[1024];       // [w][k][pp]
    __shared__ __align__(16) u64 shh[1024];
    const int tid = threadIdx.x;

    for (int i = tid; i < 4096; i += 256) {
        int r = i >> 5, k = i & 31;
        int idx = (k*32 + (r & 31))*4 + (r >> 5);
        ((float*)sWih4)[idx] = Wih[i];
        ((float*)sWhh4)[idx] = Whh[i];
    }
    if (tid < 128) ((float*)sb4)[(tid & 31)*4 + (tid >> 5)] = bih[tid] + bhh[tid];
    __syncthreads();

    const int lane = tid & 31;
    const int w = tid >> 5;
    const int n0 = blockIdx.x * 64 + w * 8;

    float h[8], c[8];
    #pragma unroll
    for (int r = 0; r < 8; r++) { h[r] = h0[(n0+r)*32 + lane]; c[r] = c0[(n0+r)*32 + lane]; }

    const float4 bb = sb4[lane];
    u64 bd[4];
    PACK2(bd[0], bb.x, bb.x); PACK2(bd[1], bb.y, bb.y);
    PACK2(bd[2], bb.z, bb.z); PACK2(bd[3], bb.w, bb.w);

    #pragma unroll 1
    for (int t = 0; t < TT; t++) {
        __syncwarp();
        #pragma unroll
        for (int pr = 0; pr < 4; pr++) {
            float x0 = g_graph_in[((size_t)t*NN + n0 + 2*pr    )*32 + lane];
            float x1 = g_graph_in[((size_t)t*NN + n0 + 2*pr + 1)*32 + lane];
            u64 xq, hq;
            PACK2(xq, x0, x1);
            PACK2(hq, h[2*pr], h[2*pr+1]);
            shx[(w*32 + lane)*4 + pr] = xq;
            shh[(w*32 + lane)*4 + pr] = hq;
        }
        __syncwarp();

        u64 ac[16];   // [g*4 + pp]
        #pragma unroll
        for (int g = 0; g < 4; g++) {
            ac[g*4] = bd[g]; ac[g*4+1] = bd[g]; ac[g*4+2] = bd[g]; ac[g*4+3] = bd[g];
        }

        #pragma unroll
        for (int k = 0; k < 32; k++) {
            float4 wi = sWih4[k*32 + lane];
            float4 wh = sWhh4[k*32 + lane];
            ulonglong2 xa = *(const ulonglong2*)&shx[(w*32 + k)*4];
            ulonglong2 xb = *(const ulonglong2*)&shx[(w*32 + k)*4 + 2];
            ulonglong2 ha = *(const ulonglong2*)&shh[(w*32 + k)*4];
            ulonglong2 hb = *(const ulonglong2*)&shh[(w*32 + k)*4 + 2];
            u64 d;
            PACK2(d, wi.x, wi.x);
            FMA2(ac[0],  xa.x, d); FMA2(ac[1],  xa.y, d); FMA2(ac[2],  xb.x, d); FMA2(ac[3],  xb.y, d);
            PACK2(d, wi.y, wi.y);
            FMA2(ac[4],  xa.x, d); FMA2(ac[5],  xa.y, d); FMA2(ac[6],  xb.x, d); FMA2(ac[7],  xb.y, d);
            PACK2(d, wi.z, wi.z);
            FMA2(ac[8],  xa.x, d); FMA2(ac[9],  xa.y, d); FMA2(ac[10], xb.x, d); FMA2(ac[11], xb.y, d);
            PACK2(d, wi.w, wi.w);
            FMA2(ac[12], xa.x, d); FMA2(ac[13], xa.y, d); FMA2(ac[14], xb.x, d); FMA2(ac[15], xb.y, d);
            PACK2(d, wh.x, wh.x);
            FMA2(ac[0],  ha.x, d); FMA2(ac[1],  ha.y, d); FMA2(ac[2],  hb.x, d); FMA2(ac[3],  hb.y, d);
            PACK2(d, wh.y, wh.y);
            FMA2(ac[4],  ha.x, d); FMA2(ac[5],  ha.y, d); FMA2(ac[6],  hb.x, d); FMA2(ac[7],  hb.y, d);
            PACK2(d, wh.z, wh.z);
            FMA2(ac[8],  ha.x, d); FMA2(ac[9],  ha.y, d); FMA2(ac[10], hb.x, d); FMA2(ac[11], hb.y, d);
            PACK2(d, wh.w, wh.w);
            FMA2(ac[12], ha.x, d); FMA2(ac[13], ha.y, d); FMA2(ac[14], hb.x, d); FMA2(ac[15], hb.y, d);
        }

        #pragma unroll
        for (int pr = 0; pr < 4; pr++) {
            float A0a, A0b, A1a, A1b, A2a, A2b, A3a, A3b;
            UNPACK2(A0a, A0b, ac[0*4 + pr]);
            UNPACK2(A1a, A1b, ac[1*4 + pr]);
            UNPACK2(A2a, A2b, ac[2*4 + pr]);
            UNPACK2(A3a, A3b, ac[3*4 + pr]);
            int r0 = 2*pr, r1 = 2*pr + 1;
            c[r0] = sig_fast(A1a) * c[r0] + sig_fast(A0a) * tanh_fast(A2a);
            h[r0] = sig_fast(A3a) * tanh_fast(c[r0]);
            c[r1] = sig_fast(A1b) * c[r1] + sig_fast(A0b) * tanh_fast(A2b);
            h[r1] = sig_fast(A3b) * tanh_fast(c[r1]);
            hs[((size_t)t*NN + n0 + r0)*32 + lane] = h[r0];
            hs[((size_t)t*NN + n0 + r1)*32 + lane] = h[r1];
        }
    }
}

// ---------------------------------------------------------------------------
// Concat (float4): encoded[n] = [traj_hs[7,n] | graph_hs[7,n] | z[n/64]]
// ---------------------------------------------------------------------------
__global__ void concat_kernel(const float* __restrict__ z,
        const float* __restrict__ traj, const float* __restrict__ graph,
        float* __restrict__ out)
{
    int idx = blockIdx.x * blockDim.x + threadIdx.x;
    if (idx >= NN*18) return;
    int n = idx / 18, j = idx - n*18;
    float4 v;
    if (j < 8)       v = ((const float4*)traj)[((size_t)7*NN + n)*8 + j];
    else if (j < 16) v = ((const float4*)graph)[((size_t)7*NN + n)*8 + (j - 8)];
    else             v = ((const float4*)z)[(n >> 6)*2 + (j - 16)];
    ((float4*)out)[idx] = v;
}

extern "C" void kernel_launch(void* const* d_in, const int* in_sizes, int n_in,
                              void* d_out, int out_size) {
    const float* obs  = (const float*)d_in[0];
    const float* h0t  = (const float*)d_in[1];
    const float* c0t  = (const float*)d_in[2];
    const float* h0g  = (const float*)d_in[3];
    const float* c0g  = (const float*)d_in[4];
    const float* z    = (const float*)d_in[5];
    const float* WihT = (const float*)d_in[6];
    const float* WhhT = (const float*)d_in[7];
    const float* bihT = (const float*)d_in[8];
    const float* bhhT = (const float*)d_in[9];
    const float* WihG = (const float*)d_in[10];
    const float* WhhG = (const float*)d_in[11];
    const float* bihG = (const float*)d_in[12];
    const float* bhhG = (const float*)d_in[13];
    const float* w0   = (const float*)d_in[14];
    const float* as0  = (const float*)d_in[15];
    const float* ad0  = (const float*)d_in[16];
    const float* b0   = (const float*)d_in[17];
    const float* w1   = (const float*)d_in[18];
    const float* as1  = (const float*)d_in[19];
    const float* ad1  = (const float*)d_in[20];
    const float* b1   = (const float*)d_in[21];
    float* out = (float*)d_out;

    float* traj_hs;
    float* graph_hs;
    if (out_size >= ENC_ELEMS + 2*SEQ_ELEMS) {
        graph_hs = out + ENC_ELEMS;
        traj_hs  = out + ENC_ELEMS + SEQ_ELEMS;
    } else {
        void* pt = nullptr; void* pg = nullptr;
        cudaGetSymbolAddress(&pt, g_traj_fb);
        cudaGetSymbolAddress(&pg, g_graph_fb);
        traj_hs  = (float*)pt;
        graph_hs = (float*)pg;
    }

    lstm_traj_kernel<<<NN/32, 256>>>(obs, h0t, c0t, WihT, WhhT, bihT, bhhT, traj_hs);
    gat0_kernel<<<SS*TT, 256>>>(traj_hs, w0, as0, ad0, b0);
    gat1_kernel<<<SS*TT, 256>>>(w1, as1, ad1, b1);
    lstm_graph_kernel<<<NN/64, 256>>>(h0g, c0g, WihG, WhhG, bihG, bhhG, graph_hs);
    concat_kernel<<<(NN*18 + 255)/256, 256>>>(z, traj_hs, graph_hs, out);
}

// round 12
// speedup vs baseline: 1.0836x; 1.0836x over previous
#include <cuda_runtime.h>
#include <math.h>

#define SS 512
#define PP 64
#define TT 8
#define NN (SS*PP)            // 32768

#define ENC_ELEMS (NN*72)     // 2359296
#define SEQ_ELEMS (TT*NN*32)  // 8388608

#define AST 68                // padded attention row stride (floats)

typedef unsigned long long u64;

__device__ float g_graph_in[SEQ_ELEMS];        // GAT output -> graph LSTM input
__device__ float g_x2[(size_t)SS*TT*64*64];    // GAT layer0 output (elu'd)
__device__ float g_traj_fb[SEQ_ELEMS];
__device__ float g_graph_fb[SEQ_ELEMS];

__device__ __forceinline__ float tanh_fast(float x){
    float y; asm("tanh.approx.f32 %0, %1;" : "=f"(y) : "f"(x)); return y;
}
__device__ __forceinline__ float sig_fast(float x){
    return 0.5f * tanh_fast(0.5f * x) + 0.5f;
}
__device__ __forceinline__ void fma4(float4& a, float s, const float4 w){
    a.x += s*w.x; a.y += s*w.y; a.z += s*w.z; a.w += s*w.w;
}

#define FMA2(d, a, b) asm("fma.rn.f32x2 %0, %1, %2, %0;" : "+l"(d) : "l"(a), "l"(b))
#define PACK2(d, lo, hi) asm("mov.b64 %0, {%1, %2};" : "=l"(d) : "f"(lo), "f"(hi))
#define UNPACK2(lo, hi, s) asm("mov.b64 {%0, %1}, %2;" : "=f"(lo), "=f"(hi) : "l"(s))

// ---------------------------------------------------------------------------
// LSTM traj: input 3, hidden 32, T=8. Warp = 4 peds (2 f32x2 pairs).
// (unchanged — measured good)
// ---------------------------------------------------------------------------
__global__ void lstm_traj_kernel(const float* __restrict__ x,
        const float* __restrict__ h0, const float* __restrict__ c0,
        const float* __restrict__ Wih, const float* __restrict__ Whh,
        const float* __restrict__ bih, const float* __restrict__ bhh,
        float* __restrict__ hs)
{
    __shared__ __align__(16) float4 sWhh4[1024];  // [k][lane] -> gates
    __shared__ __align__(16) float4 sWihP[96];    // [j=0..2][lane] -> gates
    __shared__ __align__(16) float4 sb4[32];
    __shared__ __align__(8)  float shhf[1024];    // [w][pp][k][c] pair-interleaved
    const int tid = threadIdx.x;

    for (int i = tid; i < 4096; i += 256) {
        int r = i >> 5, k = i & 31;
        ((float*)sWhh4)[(k*32 + (r & 31))*4 + (r >> 5)] = Whh[i];
    }
    for (int i = tid; i < 384; i += 256) {
        int r = i / 3, j = i - r*3;
        ((float*)sWihP)[(j*32 + (r & 31))*4 + (r >> 5)] = Wih[i];
    }
    if (tid < 128) ((float*)sb4)[(tid & 31)*4 + (tid >> 5)] = bih[tid] + bhh[tid];
    __syncthreads();

    const int lane = tid & 31;
    const int w2 = (tid >> 5) * 2;
    const int n0 = blockIdx.x * 32 + w2 * 2;

    float h[4], c[4];
    #pragma unroll
    for (int r = 0; r < 4; r++) { h[r] = h0[(n0+r)*32 + lane]; c[r] = c0[(n0+r)*32 + lane]; }

    const float4 bb = sb4[lane];
    u64 bd[4];
    PACK2(bd[0], bb.x, bb.x); PACK2(bd[1], bb.y, bb.y);
    PACK2(bd[2], bb.z, bb.z); PACK2(bd[3], bb.w, bb.w);

    const u64* hp0 = (const u64*)shhf + (w2 + 0)*32;
    const u64* hp1 = (const u64*)shhf + (w2 + 1)*32;

    #pragma unroll 1
    for (int t = 0; t < TT; t++) {
        __syncwarp();
        #pragma unroll
        for (int r = 0; r < 4; r++)
            shhf[((w2 + (r>>1))*32 + lane)*2 + (r&1)] = h[r];
        __syncwarp();

        u64 ac[8];
        #pragma unroll
        for (int g = 0; g < 4; g++) { ac[g*2] = bd[g]; ac[g*2+1] = bd[g]; }

        const float* xp = x + ((size_t)t*NN + n0) * 3;
        #pragma unroll
        for (int j = 0; j < 3; j++) {
            float4 wj = sWihP[j*32 + lane];
            u64 xq0, xq1, d0, d1, d2, d3;
            PACK2(xq0, xp[0*3+j], xp[1*3+j]);
            PACK2(xq1, xp[2*3+j], xp[3*3+j]);
            PACK2(d0, wj.x, wj.x); PACK2(d1, wj.y, wj.y);
            PACK2(d2, wj.z, wj.z); PACK2(d3, wj.w, wj.w);
            FMA2(ac[0], xq0, d0); FMA2(ac[1], xq1, d0);
            FMA2(ac[2], xq0, d1); FMA2(ac[3], xq1, d1);
            FMA2(ac[4], xq0, d2); FMA2(ac[5], xq1, d2);
            FMA2(ac[6], xq0, d3); FMA2(ac[7], xq1, d3);
        }

        #pragma unroll
        for (int k = 0; k < 32; k++) {
            float4 wh = sWhh4[k*32 + lane];
            u64 hq0 = hp0[k], hq1 = hp1[k];
            u64 d0, d1, d2, d3;
            PACK2(d0, wh.x, wh.x); PACK2(d1, wh.y, wh.y);
            PACK2(d2, wh.z, wh.z); PACK2(d3, wh.w, wh.w);
            FMA2(ac[0], hq0, d0); FMA2(ac[1], hq1, d0);
            FMA2(ac[2], hq0, d1); FMA2(ac[3], hq1, d1);
            FMA2(ac[4], hq0, d2); FMA2(ac[5], hq1, d2);
            FMA2(ac[6], hq0, d3); FMA2(ac[7], hq1, d3);
        }

        float A[4][4];
        #pragma unroll
        for (int g = 0; g < 4; g++) {
            UNPACK2(A[g][0], A[g][1], ac[g*2]);
            UNPACK2(A[g][2], A[g][3], ac[g*2+1]);
        }
        #pragma unroll
        for (int r = 0; r < 4; r++) {
            c[r] = sig_fast(A[1][r]) * c[r] + sig_fast(A[0][r]) * tanh_fast(A[2][r]);
            h[r] = sig_fast(A[3][r]) * tanh_fast(c[r]);
            hs[((size_t)t*NN + n0 + r)*32 + lane] = h[r];
        }
    }
}

// ---------------------------------------------------------------------------
// GAT layer 0: parallel norm-stats + FMA2 matmul/apply + padded attn
// ---------------------------------------------------------------------------
__global__ void gat0_kernel(const float* __restrict__ traj,
        const float* __restrict__ w0, const float* __restrict__ as0,
        const float* __restrict__ ad0, const float* __restrict__ b0)
{
    __shared__ __align__(16) float pool[4416];  // x | w ; later attn[64][AST]
    __shared__ __align__(16) float shp[4096];   // stats partials, then hp[p][h*16+o]
    __shared__ float sS[256], sD[256];
    __shared__ __align__(16) float smean[32], sinv[32];
    __shared__ float srinv[64];
    __shared__ float sas[64], sad[64];
    __shared__ __align__(16) float4 sb0v[4];

    float4* sx4 = (float4*)pool;            // 512 float4
    float4* sw4 = (float4*)(pool + 2048);   // 512 float4: w(h,f,o4) at h*128+f*4+o4
    const int tid = threadIdx.x;
    const int b = blockIdx.x, sIdx = b >> 3, tIdx = b & 7;

    {
        const float4* src = (const float4*)(traj + ((size_t)tIdx*NN + sIdx*64) * 32);
        for (int i = tid; i < 512; i += 256) sx4[i] = src[i];
        const float4* wsrc = (const float4*)w0;
        for (int i = tid; i < 512; i += 256) sw4[i] = wsrc[i];
        if (tid < 64) { sas[tid] = as0[tid]; sad[tid] = ad0[tid]; }
        if (tid < 4)  sb0v[tid] = ((const float4*)b0)[tid];
    }
    __syncthreads();

    // instance norm stats: all warps produce partials (lane=feature, warp=ped-group)
    {
        int f = tid & 31, g = tid >> 5;   // 8 groups of 8 peds
        const float* xs = pool;
        float s = 0.f, s2 = 0.f;
        #pragma unroll
        for (int i = 0; i < 8; i++) { float v = xs[(g*8+i)*32 + f]; s += v; s2 += v*v; }
        shp[g*32 + f] = s;
        shp[256 + g*32 + f] = s2;
    }
    __syncthreads();
    if (tid < 32) {
        float s = 0.f, s2 = 0.f;
        #pragma unroll
        for (int g = 0; g < 8; g++) { s += shp[g*32 + tid]; s2 += shp[256 + g*32 + tid]; }
        float m = s * (1.0f/64.0f);
        float var = s2 * (1.0f/64.0f) - m*m;
        smean[tid] = m; sinv[tid] = rsqrtf(var + 1e-5f);
    }
    __syncthreads();
    for (int i = tid; i < 512; i += 256) {
        int f4 = i & 7;
        float4 m4 = ((float4*)smean)[f4], i4 = ((float4*)sinv)[f4];
        float4 v = sx4[i];
        v.x = (v.x - m4.x)*i4.x; v.y = (v.y - m4.y)*i4.y;
        v.z = (v.z - m4.z)*i4.z; v.w = (v.w - m4.w)*i4.w;
        sx4[i] = v;
    }
    __syncthreads();

    // hp matmul with FMA2 pair accumulators
    for (int it = tid; it < 1024; it += 256) {
        int p = it >> 4, j = it & 15, hh = j >> 2, o4 = j & 3;
        u64 a01 = 0ull, a23 = 0ull;
        #pragma unroll
        for (int f4 = 0; f4 < 8; f4++) {
            float4 xv = sx4[p*8 + f4];
            const ulonglong2* wp = (const ulonglong2*)&sw4[hh*128 + (f4*4)*4 + o4];
            u64 xd;
            ulonglong2 wv;
            PACK2(xd, xv.x, xv.x); wv = wp[0];
            FMA2(a01, xd, wv.x); FMA2(a23, xd, wv.y);
            PACK2(xd, xv.y, xv.y); wv = wp[4];
            FMA2(a01, xd, wv.x); FMA2(a23, xd, wv.y);
            PACK2(xd, xv.z, xv.z); wv = wp[8];
            FMA2(a01, xd, wv.x); FMA2(a23, xd, wv.y);
            PACK2(xd, xv.w, xv.w); wv = wp[12];
            FMA2(a01, xd, wv.x); FMA2(a23, xd, wv.y);
        }
        u64* dst = (u64*)shp + (p*16 + hh*4 + o4)*2;
        dst[0] = a01; dst[1] = a23;
    }
    __syncthreads();

    // s[h][p], d[h][p]
    {
        int hh = tid >> 6, p = tid & 63;
        const float4* hp4 = (const float4*)shp;
        float as = 0.f, ad = 0.f;
        #pragma unroll
        for (int o4 = 0; o4 < 4; o4++) {
            float4 v = hp4[p*16 + hh*4 + o4];
            int ob = hh*16 + o4*4;
            as += v.x*sas[ob] + v.y*sas[ob+1] + v.z*sas[ob+2] + v.w*sas[ob+3];
            ad += v.x*sad[ob] + v.y*sad[ob+1] + v.z*sad[ob+2] + v.w*sad[ob+3];
        }
        sS[tid] = as; sD[tid] = ad;
    }
    __syncthreads();

    float* sattn = pool;  // [64][AST], overlays x+w (both dead)

    for (int hh = 0; hh < 4; hh++) {
        // softmax: 4 threads per row
        {
            int p = tid >> 2, q = tid & 3;
            float sp = sS[hh*64 + p];
            float l[16]; float mx = -1e30f;
            #pragma unroll
            for (int mm = 0; mm < 16; mm++) {
                float v = sp + sD[hh*64 + q*16 + mm];
                v = (v > 0.f) ? v : 0.2f*v;
                l[mm] = v; mx = fmaxf(mx, v);
            }
            mx = fmaxf(mx, __shfl_xor_sync(0xffffffffu, mx, 1));
            mx = fmaxf(mx, __shfl_xor_sync(0xffffffffu, mx, 2));
            float sum = 0.f;
            #pragma unroll
            for (int mm = 0; mm < 16; mm++) {
                float e = __expf(l[mm] - mx);
                sattn[p*AST + q*16 + mm] = e; sum += e;
            }
            sum += __shfl_xor_sync(0xffffffffu, sum, 1);
            sum += __shfl_xor_sync(0xffffffffu, sum, 2);
            if (q == 0) srinv[p] = 1.0f / sum;
        }
        __syncthreads();
        // apply with FMA2: thread = (p, o4)
        {
            int p = tid >> 2, o4 = tid & 3;
            const float* ap = &sattn[p*AST];
            const ulonglong2* hp2 = (const ulonglong2*)shp;
            u64 a01 = 0ull, a23 = 0ull;
            #pragma unroll
            for (int m = 0; m < 64; m++) {
                u64 ad; PACK2(ad, ap[m], ap[m]);
                ulonglong2 hv = hp2[m*16 + hh*4 + o4];
                FMA2(a01, ad, hv.x); FMA2(a23, ad, hv.y);
            }
            float4 acc;
            UNPACK2(acc.x, acc.y, a01);
            UNPACK2(acc.z, acc.w, a23);
            float ri = srinv[p];
            float4 bb = sb0v[o4];
            float4 res;
            res.x = acc.x*ri + bb.x; res.y = acc.y*ri + bb.y;
            res.z = acc.z*ri + bb.z; res.w = acc.w*ri + bb.w;
            res.x = (res.x > 0.f) ? res.x : (__expf(res.x) - 1.f);
            res.y = (res.y > 0.f) ? res.y : (__expf(res.y) - 1.f);
            res.z = (res.z > 0.f) ? res.z : (__expf(res.z) - 1.f);
            res.w = (res.w > 0.f) ? res.w : (__expf(res.w) - 1.f);
            ((float4*)g_x2)[((size_t)b*64 + p)*16 + hh*4 + o4] = res;
        }
        __syncthreads();
    }
}

// ---------------------------------------------------------------------------
// GAT layer 1: parallel norm-stats + FMA2 matmul/apply + padded attn
// ---------------------------------------------------------------------------
__global__ void gat1_kernel(const float* __restrict__ w1, const float* __restrict__ as1,
        const float* __restrict__ ad1, const float* __restrict__ b1)
{
    __shared__ __align__(16) float pool[4416];
    __shared__ __align__(16) float sw[2048];
    __shared__ __align__(16) float shp[2048];
    __shared__ float sS[64], sD[64];
    __shared__ __align__(16) float smean[64], sinv[64];
    __shared__ float srinv[64], sas[32], sad[32];
    __shared__ __align__(16) float4 sb1v[8];

    float4* sx4 = (float4*)pool;
    float4* sw4 = (float4*)sw;
    const int tid = threadIdx.x;
    const int b = blockIdx.x, sIdx = b >> 3, tIdx = b & 7;

    {
        const float4* src = (const float4*)(g_x2 + (size_t)b*4096);
        for (int i = tid; i < 1024; i += 256) sx4[i] = src[i];
        const float4* wsrc = (const float4*)w1;
        for (int i = tid; i < 512; i += 256) sw4[i] = wsrc[i];
        if (tid < 32) { sas[tid] = as1[tid]; sad[tid] = ad1[tid]; }
        if (tid < 8)  sb1v[tid] = ((const float4*)b1)[tid];
    }
    __syncthreads();

    // parallel stats: f = tid&63, group g = tid>>6 covers 16 peds
    {
        int f = tid & 63, g = tid >> 6;
        float s = 0.f, s2 = 0.f;
        #pragma unroll
        for (int i = 0; i < 16; i++) { float v = pool[(g*16+i)*64 + f]; s += v; s2 += v*v; }
        shp[g*64 + f] = s;
        shp[256 + g*64 + f] = s2;
    }
    __syncthreads();
    if (tid < 64) {
        float s = 0.f, s2 = 0.f;
        #pragma unroll
        for (int g = 0; g < 4; g++) { s += shp[g*64 + tid]; s2 += shp[256 + g*64 + tid]; }
        float m = s * (1.0f/64.0f);
        float var = s2 * (1.0f/64.0f) - m*m;
        smean[tid] = m; sinv[tid] = rsqrtf(var + 1e-5f);
    }
    __syncthreads();
    for (int i = tid; i < 1024; i += 256) {
        int f4 = i & 15;
        float4 m4 = ((float4*)smean)[f4], i4 = ((float4*)sinv)[f4];
        float4 v = sx4[i];
        v.x = (v.x - m4.x)*i4.x; v.y = (v.y - m4.y)*i4.y;
        v.z = (v.z - m4.z)*i4.z; v.w = (v.w - m4.w)*i4.w;
        sx4[i] = v;
    }
    __syncthreads();

    // hp matmul with FMA2
    for (int it = tid; it < 512; it += 256) {
        int p = it >> 3, o4 = it & 7;
        u64 a01 = 0ull, a23 = 0ull;
        #pragma unroll
        for (int f4 = 0; f4 < 16; f4++) {
            float4 xv = sx4[p*16 + f4];
            const ulonglong2* wp = (const ulonglong2*)&sw4[(f4*4)*8 + o4];
            u64 xd;
            ulonglong2 wv;
            PACK2(xd, xv.x, xv.x); wv = wp[0];
            FMA2(a01, xd, wv.x); FMA2(a23, xd, wv.y);
            PACK2(xd, xv.y, xv.y); wv = wp[8];
            FMA2(a01, xd, wv.x); FMA2(a23, xd, wv.y);
            PACK2(xd, xv.z, xv.z); wv = wp[16];
            FMA2(a01, xd, wv.x); FMA2(a23, xd, wv.y);
            PACK2(xd, xv.w, xv.w); wv = wp[24];
            FMA2(a01, xd, wv.x); FMA2(a23, xd, wv.y);
        }
        u64* dst = (u64*)shp + (p*8 + o4)*2;
        dst[0] = a01; dst[1] = a23;
    }
    __syncthreads();

    if (tid < 64) {
        int p = tid;
        const float4* hp4 = (const float4*)shp;
        float as = 0.f, ad = 0.f;
        #pragma unroll
        for (int o4 = 0; o4 < 8; o4++) {
            float4 v = hp4[p*8 + o4];
            as += v.x*sas[o4*4] + v.y*sas[o4*4+1] + v.z*sas[o4*4+2] + v.w*sas[o4*4+3];
            ad += v.x*sad[o4*4] + v.y*sad[o4*4+1] + v.z*sad[o4*4+2] + v.w*sad[o4*4+3];
        }
        sS[p] = as; sD[p] = ad;
    }
    __syncthreads();

    float* sattn = pool;
    {
        int p = tid >> 2, q = tid & 3;
        float sp = sS[p];
        float l[16]; float mx = -1e30f;
        #pragma unroll
        for (int mm = 0; mm < 16; mm++) {
            float v = sp + sD[q*16 + mm];
            v = (v > 0.f) ? v : 0.2f*v;
            l[mm] = v; mx = fmaxf(mx, v);
        }
        mx = fmaxf(mx, __shfl_xor_sync(0xffffffffu, mx, 1));
        mx = fmaxf(mx, __shfl_xor_sync(0xffffffffu, mx, 2));
        float sum = 0.f;
        #pragma unroll
        for (int mm = 0; mm < 16; mm++) {
            float e = __expf(l[mm] - mx);
            sattn[p*AST + q*16 + mm] = e; sum += e;
        }
        sum += __shfl_xor_sync(0xffffffffu, sum, 1);
        sum += __shfl_xor_sync(0xffffffffu, sum, 2);
        if (q == 0) srinv[p] = 1.0f / sum;
    }
    __syncthreads();

    // apply with FMA2
    for (int it = tid; it < 512; it += 256) {
        int p = it >> 3, o4 = it & 7;
        const float* ap = &sattn[p*AST];
        const ulonglong2* hp2 = (const ulonglong2*)shp;
        u64 a01 = 0ull, a23 = 0ull;
        #pragma unroll
        for (int m = 0; m < 64; m++) {
            u64 ad; PACK2(ad, ap[m], ap[m]);
            ulonglong2 hv = hp2[m*8 + o4];
            FMA2(a01, ad, hv.x); FMA2(a23, ad, hv.y);
        }
        float4 acc;
        UNPACK2(acc.x, acc.y, a01);
        UNPACK2(acc.z, acc.w, a23);
        float ri = srinv[p];
        float4 bb = sb1v[o4];
        float4 res;
        res.x = acc.x*ri + bb.x; res.y = acc.y*ri + bb.y;
        res.z = acc.z*ri + bb.z; res.w = acc.w*ri + bb.w;
        ((float4*)g_graph_in)[((size_t)tIdx*NN + sIdx*64 + p)*8 + o4] = res;
    }
}

// ---------------------------------------------------------------------------
// LSTM graph (fused x+h): input 32, hidden 32. Warp = 8 peds (4 f32x2 pairs).
// (unchanged from R11 — measured 110 us)
// ---------------------------------------------------------------------------
__global__ void lstm_graph_kernel(
        const float* __restrict__ h0, const float* __restrict__ c0,
        const float* __restrict__ Wih, const float* __restrict__ Whh,
        const float* __restrict__ bih, const float* __restrict__ bhh,
        float* __restrict__ hs)
{
    __shared__ __align__(16) float4 sWih4[1024];  // [k][lane] -> gates
    __shared__ __align__(16) float4 sWhh4[1024];
    __shared__ __align__(16) float4 sb4[32];
    __shared__ __align__(16) u64 shx[1024];       // [w][k][pp]
    __shared__ __align__(16) u64 shh[1024];
    const int tid = threadIdx.x;

    for (int i = tid; i < 4096; i += 256) {
        int r = i >> 5, k = i & 31;
        int idx = (k*32 + (r & 31))*4 + (r >> 5);
        ((float*)sWih4)[idx] = Wih[i];
        ((float*)sWhh4)[idx] = Whh[i];
    }
    if (tid < 128) ((float*)sb4)[(tid & 31)*4 + (tid >> 5)] = bih[tid] + bhh[tid];
    __syncthreads();

    const int lane = tid & 31;
    const int w = tid >> 5;
    const int n0 = blockIdx.x * 64 + w * 8;

    float h[8], c[8];
    #pragma unroll
    for (int r = 0; r < 8; r++) { h[r] = h0[(n0+r)*32 + lane]; c[r] = c0[(n0+r)*32 + lane]; }

    const float4 bb = sb4[lane];
    u64 bd[4];
    PACK2(bd[0], bb.x, bb.x); PACK2(bd[1], bb.y, bb.y);
    PACK2(bd[2], bb.z, bb.z); PACK2(bd[3], bb.w, bb.w);

    #pragma unroll 1
    for (int t = 0; t < TT; t++) {
        __syncwarp();
        #pragma unroll
        for (int pr = 0; pr < 4; pr++) {
            float x0 = g_graph_in[((size_t)t*NN + n0 + 2*pr    )*32 + lane];
            float x1 = g_graph_in[((size_t)t*NN + n0 + 2*pr + 1)*32 + lane];
            u64 xq, hq;
            PACK2(xq, x0, x1);
            PACK2(hq, h[2*pr], h[2*pr+1]);
            shx[(w*32 + lane)*4 + pr] = xq;
            shh[(w*32 + lane)*4 + pr] = hq;
        }
        __syncwarp();

        u64 ac[16];   // [g*4 + pp]
        #pragma unroll
        for (int g = 0; g < 4; g++) {
            ac[g*4] = bd[g]; ac[g*4+1] = bd[g]; ac[g*4+2] = bd[g]; ac[g*4+3] = bd[g];
        }

        #pragma unroll
        for (int k = 0; k < 32; k++) {
            float4 wi = sWih4[k*32 + lane];
            float4 wh = sWhh4[k*32 + lane];
            ulonglong2 xa = *(const ulonglong2*)&shx[(w*32 + k)*4];
            ulonglong2 xb = *(const ulonglong2*)&shx[(w*32 + k)*4 + 2];
            ulonglong2 ha = *(const ulonglong2*)&shh[(w*32 + k)*4];
            ulonglong2 hb = *(const ulonglong2*)&shh[(w*32 + k)*4 + 2];
            u64 d;
            PACK2(d, wi.x, wi.x);
            FMA2(ac[0],  xa.x, d); FMA2(ac[1],  xa.y, d); FMA2(ac[2],  xb.x, d); FMA2(ac[3],  xb.y, d);
            PACK2(d, wi.y, wi.y);
            FMA2(ac[4],  xa.x, d); FMA2(ac[5],  xa.y, d); FMA2(ac[6],  xb.x, d); FMA2(ac[7],  xb.y, d);
            PACK2(d, wi.z, wi.z);
            FMA2(ac[8],  xa.x, d); FMA2(ac[9],  xa.y, d); FMA2(ac[10], xb.x, d); FMA2(ac[11], xb.y, d);
            PACK2(d, wi.w, wi.w);
            FMA2(ac[12], xa.x, d); FMA2(ac[13], xa.y, d); FMA2(ac[14], xb.x, d); FMA2(ac[15], xb.y, d);
            PACK2(d, wh.x, wh.x);
            FMA2(ac[0],  ha.x, d); FMA2(ac[1],  ha.y, d); FMA2(ac[2],  hb.x, d); FMA2(ac[3],  hb.y, d);
            PACK2(d, wh.y, wh.y);
            FMA2(ac[4],  ha.x, d); FMA2(ac[5],  ha.y, d); FMA2(ac[6],  hb.x, d); FMA2(ac[7],  hb.y, d);
            PACK2(d, wh.z, wh.z);
            FMA2(ac[8],  ha.x, d); FMA2(ac[9],  ha.y, d); FMA2(ac[10], hb.x, d); FMA2(ac[11], hb.y, d);
            PACK2(d, wh.w, wh.w);
            FMA2(ac[12], ha.x, d); FMA2(ac[13], ha.y, d); FMA2(ac[14], hb.x, d); FMA2(ac[15], hb.y, d);
        }

        #pragma unroll
        for (int pr = 0; pr < 4; pr++) {
            float A0a, A0b, A1a, A1b, A2a, A2b, A3a, A3b;
            UNPACK2(A0a, A0b, ac[0*4 + pr]);
            UNPACK2(A1a, A1b, ac[1*4 + pr]);
            UNPACK2(A2a, A2b, ac[2*4 + pr]);
            UNPACK2(A3a, A3b, ac[3*4 + pr]);
            int r0 = 2*pr, r1 = 2*pr + 1;
            c[r0] = sig_fast(A1a) * c[r0] + sig_fast(A0a) * tanh_fast(A2a);
            h[r0] = sig_fast(A3a) * tanh_fast(c[r0]);
            c[r1] = sig_fast(A1b) * c[r1] + sig_fast(A0b) * tanh_fast(A2b);
            h[r1] = sig_fast(A3b) * tanh_fast(c[r1]);
            hs[((size_t)t*NN + n0 + r0)*32 + lane] = h[r0];
            hs[((size_t)t*NN + n0 + r1)*32 + lane] = h[r1];
        }
    }
}

// ---------------------------------------------------------------------------
// Concat (float4): encoded[n] = [traj_hs[7,n] | graph_hs[7,n] | z[n/64]]
// ---------------------------------------------------------------------------
__global__ void concat_kernel(const float* __restrict__ z,
        const float* __restrict__ traj, const float* __restrict__ graph,
        float* __restrict__ out)
{
    int idx = blockIdx.x * blockDim.x + threadIdx.x;
    if (idx >= NN*18) return;
    int n = idx / 18, j = idx - n*18;
    float4 v;
    if (j < 8)       v = ((const float4*)traj)[((size_t)7*NN + n)*8 + j];
    else if (j < 16) v = ((const float4*)graph)[((size_t)7*NN + n)*8 + (j - 8)];
    else             v = ((const float4*)z)[(n >> 6)*2 + (j - 16)];
    ((float4*)out)[idx] = v;
}

extern "C" void kernel_launch(void* const* d_in, const int* in_sizes, int n_in,
                              void* d_out, int out_size) {
    const float* obs  = (const float*)d_in[0];
    const float* h0t  = (const float*)d_in[1];
    const float* c0t  = (const float*)d_in[2];
    const float* h0g  = (const float*)d_in[3];
    const float* c0g  = (const float*)d_in[4];
    const float* z    = (const float*)d_in[5];
    const float* WihT = (const float*)d_in[6];
    const float* WhhT = (const float*)d_in[7];
    const float* bihT = (const float*)d_in[8];
    const float* bhhT = (const float*)d_in[9];
    const float* WihG = (const float*)d_in[10];
    const float* WhhG = (const float*)d_in[11];
    const float* bihG = (const float*)d_in[12];
    const float* bhhG = (const float*)d_in[13];
    const float* w0   = (const float*)d_in[14];
    const float* as0  = (const float*)d_in[15];
    const float* ad0  = (const float*)d_in[16];
    const float* b0   = (const float*)d_in[17];
    const float* w1   = (const float*)d_in[18];
    const float* as1  = (const float*)d_in[19];
    const float* ad1  = (const float*)d_in[20];
    const float* b1   = (const float*)d_in[21];
    float* out = (float*)d_out;

    float* traj_hs;
    float* graph_hs;
    if (out_size >= ENC_ELEMS + 2*SEQ_ELEMS) {
        graph_hs = out + ENC_ELEMS;
        traj_hs  = out + ENC_ELEMS + SEQ_ELEMS;
    } else {
        void* pt = nullptr; void* pg = nullptr;
        cudaGetSymbolAddress(&pt, g_traj_fb);
        cudaGetSymbolAddress(&pg, g_graph_fb);
        traj_hs  = (float*)pt;
        graph_hs = (float*)pg;
    }

    lstm_traj_kernel<<<NN/32, 256>>>(obs, h0t, c0t, WihT, WhhT, bihT, bhhT, traj_hs);
    gat0_kernel<<<SS*TT, 256>>>(traj_hs, w0, as0, ad0, b0);
    gat1_kernel<<<SS*TT, 256>>>(w1, as1, ad1, b1);
    lstm_graph_kernel<<<NN/64, 256>>>(h0g, c0g, WihG, WhhG, bihG, bhhG, graph_hs);
    concat_kernel<<<(NN*18 + 255)/256, 256>>>(z, traj_hs, graph_hs, out);
}

// round 13
// speedup vs baseline: 1.1780x; 1.0871x over previous
#include <cuda_runtime.h>
#include <math.h>

#define SS 512
#define PP 64
#define TT 8
#define NN (SS*PP)            // 32768

#define ENC_ELEMS (NN*72)     // 2359296
#define SEQ_ELEMS (TT*NN*32)  // 8388608

#define AST 68                // padded attention row stride (floats)

typedef unsigned long long u64;

__device__ float g_graph_in[SEQ_ELEMS];        // GAT output -> graph LSTM input
__device__ float g_traj_fb[SEQ_ELEMS];
__device__ float g_graph_fb[SEQ_ELEMS];

__device__ __forceinline__ float tanh_fast(float x){
    float y; asm("tanh.approx.f32 %0, %1;" : "=f"(y) : "f"(x)); return y;
}
__device__ __forceinline__ float sig_fast(float x){
    return 0.5f * tanh_fast(0.5f * x) + 0.5f;
}

#define FMA2(d, a, b) asm("fma.rn.f32x2 %0, %1, %2, %0;" : "+l"(d) : "l"(a), "l"(b))
#define PACK2(d, lo, hi) asm("mov.b64 %0, {%1, %2};" : "=l"(d) : "f"(lo), "f"(hi))
#define UNPACK2(lo, hi, s) asm("mov.b64 {%0, %1}, %2;" : "=f"(lo), "=f"(hi) : "l"(s))

// ---------------------------------------------------------------------------
// LSTM traj: input 3, hidden 32, T=8. Warp = 4 peds (2 f32x2 pairs).
// (unchanged — measured good)
// ---------------------------------------------------------------------------
__global__ void lstm_traj_kernel(const float* __restrict__ x,
        const float* __restrict__ h0, const float* __restrict__ c0,
        const float* __restrict__ Wih, const float* __restrict__ Whh,
        const float* __restrict__ bih, const float* __restrict__ bhh,
        float* __restrict__ hs)
{
    __shared__ __align__(16) float4 sWhh4[1024];  // [k][lane] -> gates
    __shared__ __align__(16) float4 sWihP[96];    // [j=0..2][lane] -> gates
    __shared__ __align__(16) float4 sb4[32];
    __shared__ __align__(8)  float shhf[1024];    // [w][pp][k][c] pair-interleaved
    const int tid = threadIdx.x;

    for (int i = tid; i < 4096; i += 256) {
        int r = i >> 5, k = i & 31;
        ((float*)sWhh4)[(k*32 + (r & 31))*4 + (r >> 5)] = Whh[i];
    }
    for (int i = tid; i < 384; i += 256) {
        int r = i / 3, j = i - r*3;
        ((float*)sWihP)[(j*32 + (r & 31))*4 + (r >> 5)] = Wih[i];
    }
    if (tid < 128) ((float*)sb4)[(tid & 31)*4 + (tid >> 5)] = bih[tid] + bhh[tid];
    __syncthreads();

    const int lane = tid & 31;
    const int w2 = (tid >> 5) * 2;
    const int n0 = blockIdx.x * 32 + w2 * 2;

    float h[4], c[4];
    #pragma unroll
    for (int r = 0; r < 4; r++) { h[r] = h0[(n0+r)*32 + lane]; c[r] = c0[(n0+r)*32 + lane]; }

    const float4 bb = sb4[lane];
    u64 bd[4];
    PACK2(bd[0], bb.x, bb.x); PACK2(bd[1], bb.y, bb.y);
    PACK2(bd[2], bb.z, bb.z); PACK2(bd[3], bb.w, bb.w);

    const u64* hp0 = (const u64*)shhf + (w2 + 0)*32;
    const u64* hp1 = (const u64*)shhf + (w2 + 1)*32;

    #pragma unroll 1
    for (int t = 0; t < TT; t++) {
        __syncwarp();
        #pragma unroll
        for (int r = 0; r < 4; r++)
            shhf[((w2 + (r>>1))*32 + lane)*2 + (r&1)] = h[r];
        __syncwarp();

        u64 ac[8];
        #pragma unroll
        for (int g = 0; g < 4; g++) { ac[g*2] = bd[g]; ac[g*2+1] = bd[g]; }

        const float* xp = x + ((size_t)t*NN + n0) * 3;
        #pragma unroll
        for (int j = 0; j < 3; j++) {
            float4 wj = sWihP[j*32 + lane];
            u64 xq0, xq1, d0, d1, d2, d3;
            PACK2(xq0, xp[0*3+j], xp[1*3+j]);
            PACK2(xq1, xp[2*3+j], xp[3*3+j]);
            PACK2(d0, wj.x, wj.x); PACK2(d1, wj.y, wj.y);
            PACK2(d2, wj.z, wj.z); PACK2(d3, wj.w, wj.w);
            FMA2(ac[0], xq0, d0); FMA2(ac[1], xq1, d0);
            FMA2(ac[2], xq0, d1); FMA2(ac[3], xq1, d1);
            FMA2(ac[4], xq0, d2); FMA2(ac[5], xq1, d2);
            FMA2(ac[6], xq0, d3); FMA2(ac[7], xq1, d3);
        }

        #pragma unroll
        for (int k = 0; k < 32; k++) {
            float4 wh = sWhh4[k*32 + lane];
            u64 hq0 = hp0[k], hq1 = hp1[k];
            u64 d0, d1, d2, d3;
            PACK2(d0, wh.x, wh.x); PACK2(d1, wh.y, wh.y);
            PACK2(d2, wh.z, wh.z); PACK2(d3, wh.w, wh.w);
            FMA2(ac[0], hq0, d0); FMA2(ac[1], hq1, d0);
            FMA2(ac[2], hq0, d1); FMA2(ac[3], hq1, d1);
            FMA2(ac[4], hq0, d2); FMA2(ac[5], hq1, d2);
            FMA2(ac[6], hq0, d3); FMA2(ac[7], hq1, d3);
        }

        float A[4][4];
        #pragma unroll
        for (int g = 0; g < 4; g++) {
            UNPACK2(A[g][0], A[g][1], ac[g*2]);
            UNPACK2(A[g][2], A[g][3], ac[g*2+1]);
        }
        #pragma unroll
        for (int r = 0; r < 4; r++) {
            c[r] = sig_fast(A[1][r]) * c[r] + sig_fast(A[0][r]) * tanh_fast(A[2][r]);
            h[r] = sig_fast(A[3][r]) * tanh_fast(c[r]);
            hs[((size_t)t*NN + n0 + r)*32 + lane] = h[r];
        }
    }
}

// ---------------------------------------------------------------------------
// FUSED GAT: layer0 (4 heads) + layer1 in one kernel per graph block.
// sA: x | w0 -> attn (stride 68) -> [w1 | hp1] -> (hp1 kept)
// sB: stats partials -> hp0 quads -> x2 (overwritten per head) -> attn2
// ---------------------------------------------------------------------------
__global__ void gat_fused_kernel(const float* __restrict__ traj,
        const float* __restrict__ w0, const float* __restrict__ as0,
        const float* __restrict__ ad0, const float* __restrict__ b0,
        const float* __restrict__ w1, const float* __restrict__ as1,
        const float* __restrict__ ad1, const float* __restrict__ b1)
{
    __shared__ __align__(16) float sA[4416];
    __shared__ __align__(16) float sB[4416];
    __shared__ float sS[256], sD[256];
    __shared__ __align__(16) float smean[64], sinv[64];
    __shared__ float srinv[64];
    __shared__ float sas0[64], sad0[64], sas1[32], sad1[32];
    __shared__ __align__(16) float4 sb0v[4];
    __shared__ __align__(16) float4 sb1v[8];

    const int tid = threadIdx.x;
    const int b = blockIdx.x, sIdx = b >> 3, tIdx = b & 7;

    float4* sxA = (float4*)sA;            // x quads [0:512)
    float4* swA = (float4*)(sA + 2048);   // w0 quads [512)
    float4* hpB = (float4*)sB;            // hp0 / x2 quads

    // ---- prologue ----
    {
        const float4* src = (const float4*)(traj + ((size_t)tIdx*NN + sIdx*64) * 32);
        for (int i = tid; i < 512; i += 256) sxA[i] = src[i];
        const float4* wsrc = (const float4*)w0;
        for (int i = tid; i < 512; i += 256) swA[i] = wsrc[i];
        if (tid < 64) { sas0[tid] = as0[tid]; sad0[tid] = ad0[tid]; }
        if (tid < 32) { sas1[tid] = as1[tid]; sad1[tid] = ad1[tid]; }
        if (tid < 4)  sb0v[tid] = ((const float4*)b0)[tid];
        if (tid < 8)  sb1v[tid] = ((const float4*)b1)[tid];
    }
    __syncthreads();

    // ---- layer0 instance-norm stats (partials in sB) ----
    {
        int f = tid & 31, g = tid >> 5;
        float s = 0.f, s2 = 0.f;
        #pragma unroll
        for (int i = 0; i < 8; i++) { float v = sA[(g*8+i)*32 + f]; s += v; s2 += v*v; }
        sB[g*32 + f] = s;
        sB[256 + g*32 + f] = s2;
    }
    __syncthreads();
    if (tid < 32) {
        float s = 0.f, s2 = 0.f;
        #pragma unroll
        for (int g = 0; g < 8; g++) { s += sB[g*32 + tid]; s2 += sB[256 + g*32 + tid]; }
        float m = s * (1.0f/64.0f);
        float var = s2 * (1.0f/64.0f) - m*m;
        smean[tid] = m; sinv[tid] = rsqrtf(var + 1e-5f);
    }
    __syncthreads();
    for (int i = tid; i < 512; i += 256) {
        int f4 = i & 7;
        float4 m4 = ((float4*)smean)[f4], i4 = ((float4*)sinv)[f4];
        float4 v = sxA[i];
        v.x = (v.x - m4.x)*i4.x; v.y = (v.y - m4.y)*i4.y;
        v.z = (v.z - m4.z)*i4.z; v.w = (v.w - m4.w)*i4.w;
        sxA[i] = v;
    }
    __syncthreads();

    // ---- hp0 matmul (FMA2) into sB ----
    for (int it = tid; it < 1024; it += 256) {
        int p = it >> 4, j = it & 15, hh = j >> 2, o4 = j & 3;
        u64 a01 = 0ull, a23 = 0ull;
        #pragma unroll
        for (int f4 = 0; f4 < 8; f4++) {
            float4 xv = sxA[p*8 + f4];
            const ulonglong2* wp = (const ulonglong2*)&swA[hh*128 + (f4*4)*4 + o4];
            u64 xd;
            ulonglong2 wv;
            PACK2(xd, xv.x, xv.x); wv = wp[0];
            FMA2(a01, xd, wv.x); FMA2(a23, xd, wv.y);
            PACK2(xd, xv.y, xv.y); wv = wp[4];
            FMA2(a01, xd, wv.x); FMA2(a23, xd, wv.y);
            PACK2(xd, xv.z, xv.z); wv = wp[8];
            FMA2(a01, xd, wv.x); FMA2(a23, xd, wv.y);
            PACK2(xd, xv.w, xv.w); wv = wp[12];
            FMA2(a01, xd, wv.x); FMA2(a23, xd, wv.y);
        }
        u64* dst = (u64*)sB + (p*16 + hh*4 + o4)*2;
        dst[0] = a01; dst[1] = a23;
    }
    __syncthreads();

    // ---- s[h][p], d[h][p] ----
    {
        int hh = tid >> 6, p = tid & 63;
        float as = 0.f, ad = 0.f;
        #pragma unroll
        for (int o4 = 0; o4 < 4; o4++) {
            float4 v = hpB[p*16 + hh*4 + o4];
            int ob = hh*16 + o4*4;
            as += v.x*sas0[ob] + v.y*sas0[ob+1] + v.z*sas0[ob+2] + v.w*sas0[ob+3];
            ad += v.x*sad0[ob] + v.y*sad0[ob+1] + v.z*sad0[ob+2] + v.w*sad0[ob+3];
        }
        sS[tid] = as; sD[tid] = ad;
    }
    __syncthreads();

    // ---- heads loop: softmax into sA, apply reading sB, overwrite x2 into sB ----
    for (int hh = 0; hh < 4; hh++) {
        {
            int p = tid >> 2, q = tid & 3;
            float sp = sS[hh*64 + p];
            float l[16]; float mx = -1e30f;
            #pragma unroll
            for (int mm = 0; mm < 16; mm++) {
                float v = sp + sD[hh*64 + q*16 + mm];
                v = (v > 0.f) ? v : 0.2f*v;
                l[mm] = v; mx = fmaxf(mx, v);
            }
            mx = fmaxf(mx, __shfl_xor_sync(0xffffffffu, mx, 1));
            mx = fmaxf(mx, __shfl_xor_sync(0xffffffffu, mx, 2));
            float sum = 0.f;
            #pragma unroll
            for (int mm = 0; mm < 16; mm++) {
                float e = __expf(l[mm] - mx);
                sA[p*AST + q*16 + mm] = e; sum += e;
            }
            sum += __shfl_xor_sync(0xffffffffu, sum, 1);
            sum += __shfl_xor_sync(0xffffffffu, sum, 2);
            if (q == 0) srinv[p] = 1.0f / sum;
        }
        __syncthreads();
        // apply (reads sA attn + sB hp), result held in regs
        float4 res;
        {
            int p = tid >> 2, o4 = tid & 3;
            const float* ap = &sA[p*AST];
            const ulonglong2* hp2 = (const ulonglong2*)sB;
            u64 a01 = 0ull, a23 = 0ull;
            #pragma unroll
            for (int m = 0; m < 64; m++) {
                u64 ad; PACK2(ad, ap[m], ap[m]);
                ulonglong2 hv = hp2[m*16 + hh*4 + o4];
                FMA2(a01, ad, hv.x); FMA2(a23, ad, hv.y);
            }
            float4 acc;
            UNPACK2(acc.x, acc.y, a01);
            UNPACK2(acc.z, acc.w, a23);
            float ri = srinv[p];
            float4 bb = sb0v[o4];
            res.x = acc.x*ri + bb.x; res.y = acc.y*ri + bb.y;
            res.z = acc.z*ri + bb.z; res.w = acc.w*ri + bb.w;
            res.x = (res.x > 0.f) ? res.x : (__expf(res.x) - 1.f);
            res.y = (res.y > 0.f) ? res.y : (__expf(res.y) - 1.f);
            res.z = (res.z > 0.f) ? res.z : (__expf(res.z) - 1.f);
            res.w = (res.w > 0.f) ? res.w : (__expf(res.w) - 1.f);
        }
        __syncthreads();   // all hp reads for this head done
        {
            int p = tid >> 2, o4 = tid & 3;
            hpB[p*16 + hh*4 + o4] = res;   // x2 overwrites this head's hp region
        }
        __syncthreads();
    }
    // sB now holds x2[64][64]

    // ---- layer1 instance-norm stats (partials in sA) ----
    {
        int f = tid & 63, g = tid >> 6;
        float s = 0.f, s2 = 0.f;
        #pragma unroll
        for (int i = 0; i < 16; i++) { float v = sB[(g*16+i)*64 + f]; s += v; s2 += v*v; }
        sA[g*64 + f] = s;
        sA[256 + g*64 + f] = s2;
    }
    __syncthreads();
    if (tid < 64) {
        float s = 0.f, s2 = 0.f;
        #pragma unroll
        for (int g = 0; g < 4; g++) { s += sA[g*64 + tid]; s2 += sA[256 + g*64 + tid]; }
        float m = s * (1.0f/64.0f);
        float var = s2 * (1.0f/64.0f) - m*m;
        smean[tid] = m; sinv[tid] = rsqrtf(var + 1e-5f);
    }
    __syncthreads();
    // normalize x2 in place + load w1 into sA[0:2048]
    for (int i = tid; i < 1024; i += 256) {
        int f4 = i & 15;
        float4 m4 = ((float4*)smean)[f4], i4 = ((float4*)sinv)[f4];
        float4 v = hpB[i];
        v.x = (v.x - m4.x)*i4.x; v.y = (v.y - m4.y)*i4.y;
        v.z = (v.z - m4.z)*i4.z; v.w = (v.w - m4.w)*i4.w;
        hpB[i] = v;
    }
    for (int i = tid; i < 512; i += 256) ((float4*)sA)[i] = ((const float4*)w1)[i];
    __syncthreads();

    // ---- hp1 matmul (FMA2): reads sB x2 + sA w1 -> quads into sA[2048:4096] ----
    {
        float4* sw1q = (float4*)sA;
        for (int it = tid; it < 512; it += 256) {
            int p = it >> 3, o4 = it & 7;
            u64 a01 = 0ull, a23 = 0ull;
            #pragma unroll
            for (int f4 = 0; f4 < 16; f4++) {
                float4 xv = hpB[p*16 + f4];
                const ulonglong2* wp = (const ulonglong2*)&sw1q[(f4*4)*8 + o4];
                u64 xd;
                ulonglong2 wv;
                PACK2(xd, xv.x, xv.x); wv = wp[0];
                FMA2(a01, xd, wv.x); FMA2(a23, xd, wv.y);
                PACK2(xd, xv.y, xv.y); wv = wp[8];
                FMA2(a01, xd, wv.x); FMA2(a23, xd, wv.y);
                PACK2(xd, xv.z, xv.z); wv = wp[16];
                FMA2(a01, xd, wv.x); FMA2(a23, xd, wv.y);
                PACK2(xd, xv.w, xv.w); wv = wp[24];
                FMA2(a01, xd, wv.x); FMA2(a23, xd, wv.y);
            }
            u64* dst = (u64*)(sA + 2048) + (p*8 + o4)*2;
            dst[0] = a01; dst[1] = a23;
        }
    }
    __syncthreads();

    // ---- s1/d1 ----
    if (tid < 64) {
        int p = tid;
        const float4* hp4 = (const float4*)(sA + 2048);
        float as = 0.f, ad = 0.f;
        #pragma unroll
        for (int o4 = 0; o4 < 8; o4++) {
            float4 v = hp4[p*8 + o4];
            as += v.x*sas1[o4*4] + v.y*sas1[o4*4+1] + v.z*sas1[o4*4+2] + v.w*sas1[o4*4+3];
            ad += v.x*sad1[o4*4] + v.y*sad1[o4*4+1] + v.z*sad1[o4*4+2] + v.w*sad1[o4*4+3];
        }
        sS[p] = as; sD[p] = ad;
    }
    __syncthreads();

    // ---- softmax2 into sB (x2 dead) ----
    {
        int p = tid >> 2, q = tid & 3;
        float sp = sS[p];
        float l[16]; float mx = -1e30f;
        #pragma unroll
        for (int mm = 0; mm < 16; mm++) {
            float v = sp + sD[q*16 + mm];
            v = (v > 0.f) ? v : 0.2f*v;
            l[mm] = v; mx = fmaxf(mx, v);
        }
        mx = fmaxf(mx, __shfl_xor_sync(0xffffffffu, mx, 1));
        mx = fmaxf(mx, __shfl_xor_sync(0xffffffffu, mx, 2));
        float sum = 0.f;
        #pragma unroll
        for (int mm = 0; mm < 16; mm++) {
            float e = __expf(l[mm] - mx);
            sB[p*AST + q*16 + mm] = e; sum += e;
        }
        sum += __shfl_xor_sync(0xffffffffu, sum, 1);
        sum += __shfl_xor_sync(0xffffffffu, sum, 2);
        if (q == 0) srinv[p] = 1.0f / sum;
    }
    __syncthreads();

    // ---- apply2: reads sB attn + sA hp1 -> g_graph_in ----
    for (int it = tid; it < 512; it += 256) {
        int p = it >> 3, o4 = it & 7;
        const float* ap = &sB[p*AST];
        const ulonglong2* hp2 = (const ulonglong2*)(sA + 2048);
        u64 a01 = 0ull, a23 = 0ull;
        #pragma unroll
        for (int m = 0; m < 64; m++) {
            u64 ad; PACK2(ad, ap[m], ap[m]);
            ulonglong2 hv = hp2[m*8 + o4];
            FMA2(a01, ad, hv.x); FMA2(a23, ad, hv.y);
        }
        float4 acc;
        UNPACK2(acc.x, acc.y, a01);
        UNPACK2(acc.z, acc.w, a23);
        float ri = srinv[p];
        float4 bb = sb1v[o4];
        float4 res;
        res.x = acc.x*ri + bb.x; res.y = acc.y*ri + bb.y;
        res.z = acc.z*ri + bb.z; res.w = acc.w*ri + bb.w;
        ((float4*)g_graph_in)[((size_t)tIdx*NN + sIdx*64 + p)*8 + o4] = res;
    }
}

// ---------------------------------------------------------------------------
// LSTM graph (fused x+h): input 32, hidden 32. Warp = 8 peds (4 f32x2 pairs).
// (unchanged — measured 104 us)
// ---------------------------------------------------------------------------
__global__ void lstm_graph_kernel(
        const float* __restrict__ h0, const float* __restrict__ c0,
        const float* __restrict__ Wih, const float* __restrict__ Whh,
        const float* __restrict__ bih, const float* __restrict__ bhh,
        float* __restrict__ hs)
{
    __shared__ __align__(16) float4 sWih4[1024];  // [k][lane] -> gates
    __shared__ __align__(16) float4 sWhh4[1024];
    __shared__ __align__(16) float4 sb4[32];
    __shared__ __align__(16) u64 shx[1024];       // [w][k][pp]
    __shared__ __align__(16) u64 shh[1024];
    const int tid = threadIdx.x;

    for (int i = tid; i < 4096; i += 256) {
        int r = i >> 5, k = i & 31;
        int idx = (k*32 + (r & 31))*4 + (r >> 5);
        ((float*)sWih4)[idx] = Wih[i];
        ((float*)sWhh4)[idx] = Whh[i];
    }
    if (tid < 128) ((float*)sb4)[(tid & 31)*4 + (tid >> 5)] = bih[tid] + bhh[tid];
    __syncthreads();

    const int lane = tid & 31;
    const int w = tid >> 5;
    const int n0 = blockIdx.x * 64 + w * 8;

    float h[8], c[8];
    #pragma unroll
    for (int r = 0; r < 8; r++) { h[r] = h0[(n0+r)*32 + lane]; c[r] = c0[(n0+r)*32 + lane]; }

    const float4 bb = sb4[lane];
    u64 bd[4];
    PACK2(bd[0], bb.x, bb.x); PACK2(bd[1], bb.y, bb.y);
    PACK2(bd[2], bb.z, bb.z); PACK2(bd[3], bb.w, bb.w);

    #pragma unroll 1
    for (int t = 0; t < TT; t++) {
        __syncwarp();
        #pragma unroll
        for (int pr = 0; pr < 4; pr++) {
            float x0 = g_graph_in[((size_t)t*NN + n0 + 2*pr    )*32 + lane];
            float x1 = g_graph_in[((size_t)t*NN + n0 + 2*pr + 1)*32 + lane];
            u64 xq, hq;
            PACK2(xq, x0, x1);
            PACK2(hq, h[2*pr], h[2*pr+1]);
            shx[(w*32 + lane)*4 + pr] = xq;
            shh[(w*32 + lane)*4 + pr] = hq;
        }
        __syncwarp();

        u64 ac[16];   // [g*4 + pp]
        #pragma unroll
        for (int g = 0; g < 4; g++) {
            ac[g*4] = bd[g]; ac[g*4+1] = bd[g]; ac[g*4+2] = bd[g]; ac[g*4+3] = bd[g];
        }

        #pragma unroll
        for (int k = 0; k < 32; k++) {
            float4 wi = sWih4[k*32 + lane];
            float4 wh = sWhh4[k*32 + lane];
            ulonglong2 xa = *(const ulonglong2*)&shx[(w*32 + k)*4];
            ulonglong2 xb = *(const ulonglong2*)&shx[(w*32 + k)*4 + 2];
            ulonglong2 ha = *(const ulonglong2*)&shh[(w*32 + k)*4];
            ulonglong2 hb = *(const ulonglong2*)&shh[(w*32 + k)*4 + 2];
            u64 d;
            PACK2(d, wi.x, wi.x);
            FMA2(ac[0],  xa.x, d); FMA2(ac[1],  xa.y, d); FMA2(ac[2],  xb.x, d); FMA2(ac[3],  xb.y, d);
            PACK2(d, wi.y, wi.y);
            FMA2(ac[4],  xa.x, d); FMA2(ac[5],  xa.y, d); FMA2(ac[6],  xb.x, d); FMA2(ac[7],  xb.y, d);
            PACK2(d, wi.z, wi.z);
            FMA2(ac[8],  xa.x, d); FMA2(ac[9],  xa.y, d); FMA2(ac[10], xb.x, d); FMA2(ac[11], xb.y, d);
            PACK2(d, wi.w, wi.w);
            FMA2(ac[12], xa.x, d); FMA2(ac[13], xa.y, d); FMA2(ac[14], xb.x, d); FMA2(ac[15], xb.y, d);
            PACK2(d, wh.x, wh.x);
            FMA2(ac[0],  ha.x, d); FMA2(ac[1],  ha.y, d); FMA2(ac[2],  hb.x, d); FMA2(ac[3],  hb.y, d);
            PACK2(d, wh.y, wh.y);
            FMA2(ac[4],  ha.x, d); FMA2(ac[5],  ha.y, d); FMA2(ac[6],  hb.x, d); FMA2(ac[7],  hb.y, d);
            PACK2(d, wh.z, wh.z);
            FMA2(ac[8],  ha.x, d); FMA2(ac[9],  ha.y, d); FMA2(ac[10], hb.x, d); FMA2(ac[11], hb.y, d);
            PACK2(d, wh.w, wh.w);
            FMA2(ac[12], ha.x, d); FMA2(ac[13], ha.y, d); FMA2(ac[14], hb.x, d); FMA2(ac[15], hb.y, d);
        }

        #pragma unroll
        for (int pr = 0; pr < 4; pr++) {
            float A0a, A0b, A1a, A1b, A2a, A2b, A3a, A3b;
            UNPACK2(A0a, A0b, ac[0*4 + pr]);
            UNPACK2(A1a, A1b, ac[1*4 + pr]);
            UNPACK2(A2a, A2b, ac[2*4 + pr]);
            UNPACK2(A3a, A3b, ac[3*4 + pr]);
            int r0 = 2*pr, r1 = 2*pr + 1;
            c[r0] = sig_fast(A1a) * c[r0] + sig_fast(A0a) * tanh_fast(A2a);
            h[r0] = sig_fast(A3a) * tanh_fast(c[r0]);
            c[r1] = sig_fast(A1b) * c[r1] + sig_fast(A0b) * tanh_fast(A2b);
            h[r1] = sig_fast(A3b) * tanh_fast(c[r1]);
            hs[((size_t)t*NN + n0 + r0)*32 + lane] = h[r0];
            hs[((size_t)t*NN + n0 + r1)*32 + lane] = h[r1];
        }
    }
}

// ---------------------------------------------------------------------------
// Concat (float4): encoded[n] = [traj_hs[7,n] | graph_hs[7,n] | z[n/64]]
// ---------------------------------------------------------------------------
__global__ void concat_kernel(const float* __restrict__ z,
        const float* __restrict__ traj, const float* __restrict__ graph,
        float* __restrict__ out)
{
    int idx = blockIdx.x * blockDim.x + threadIdx.x;
    if (idx >= NN*18) return;
    int n = idx / 18, j = idx - n*18;
    float4 v;
    if (j < 8)       v = ((const float4*)traj)[((size_t)7*NN + n)*8 + j];
    else if (j < 16) v = ((const float4*)graph)[((size_t)7*NN + n)*8 + (j - 8)];
    else             v = ((const float4*)z)[(n >> 6)*2 + (j - 16)];
    ((float4*)out)[idx] = v;
}

extern "C" void kernel_launch(void* const* d_in, const int* in_sizes, int n_in,
                              void* d_out, int out_size) {
    const float* obs  = (const float*)d_in[0];
    const float* h0t  = (const float*)d_in[1];
    const float* c0t  = (const float*)d_in[2];
    const float* h0g  = (const float*)d_in[3];
    const float* c0g  = (const float*)d_in[4];
    const float* z    = (const float*)d_in[5];
    const float* WihT = (const float*)d_in[6];
    const float* WhhT = (const float*)d_in[7];
    const float* bihT = (const float*)d_in[8];
    const float* bhhT = (const float*)d_in[9];
    const float* WihG = (const float*)d_in[10];
    const float* WhhG = (const float*)d_in[11];
    const float* bihG = (const float*)d_in[12];
    const float* bhhG = (const float*)d_in[13];
    const float* w0   = (const float*)d_in[14];
    const float* as0  = (const float*)d_in[15];
    const float* ad0  = (const float*)d_in[16];
    const float* b0   = (const float*)d_in[17];
    const float* w1   = (const float*)d_in[18];
    const float* as1  = (const float*)d_in[19];
    const float* ad1  = (const float*)d_in[20];
    const float* b1   = (const float*)d_in[21];
    float* out = (float*)d_out;

    float* traj_hs;
    float* graph_hs;
    if (out_size >= ENC_ELEMS + 2*SEQ_ELEMS) {
        graph_hs = out + ENC_ELEMS;
        traj_hs  = out + ENC_ELEMS + SEQ_ELEMS;
    } else {
        void* pt = nullptr; void* pg = nullptr;
        cudaGetSymbolAddress(&pt, g_traj_fb);
        cudaGetSymbolAddress(&pg, g_graph_fb);
        traj_hs  = (float*)pt;
        graph_hs = (float*)pg;
    }

    lstm_traj_kernel<<<NN/32, 256>>>(obs, h0t, c0t, WihT, WhhT, bihT, bhhT, traj_hs);
    gat_fused_kernel<<<SS*TT, 256>>>(traj_hs, w0, as0, ad0, b0, w1, as1, ad1, b1);
    lstm_graph_kernel<<<NN/64, 256>>>(h0g, c0g, WihG, WhhG, bihG, bhhG, graph_hs);
    concat_kernel<<<(NN*18 + 255)/256, 256>>>(z, traj_hs, graph_hs, out);
}

// round 14
// speedup vs baseline: 1.5054x; 1.2780x over previous
#include <cuda_runtime.h>
#include <math.h>

#define SS 512
#define PP 64
#define TT 8
#define NN (SS*PP)            // 32768

#define ENC_ELEMS (NN*72)     // 2359296
#define SEQ_ELEMS (TT*NN*32)  // 8388608

#define AST 68                // padded attention row stride (floats)

typedef unsigned long long u64;

__device__ float g_graph_in[SEQ_ELEMS];        // GAT output -> graph LSTM input
__device__ float g_traj_fb[SEQ_ELEMS];
__device__ float g_graph_fb[SEQ_ELEMS];

__device__ __forceinline__ float tanh_fast(float x){
    float y; asm("tanh.approx.f32 %0, %1;" : "=f"(y) : "f"(x)); return y;
}
__device__ __forceinline__ float sig_fast(float x){
    return 0.5f * tanh_fast(0.5f * x) + 0.5f;
}

#define FMA2(d, a, b) asm("fma.rn.f32x2 %0, %1, %2, %0;" : "+l"(d) : "l"(a), "l"(b))
#define PACK2(d, lo, hi) asm("mov.b64 %0, {%1, %2};" : "=l"(d) : "f"(lo), "f"(hi))
#define UNPACK2(lo, hi, s) asm("mov.b64 {%0, %1}, %2;" : "=f"(lo), "=f"(hi) : "l"(s))

// ---------------------------------------------------------------------------
// LSTM traj: input 3, hidden 32, T=8. Warp = 8 peds (4 f32x2 pairs).
// Weight LDS amortized over 8 peds (lstm_graph R=8 structure).
// ---------------------------------------------------------------------------
__global__ void lstm_traj_kernel(const float* __restrict__ x,
        const float* __restrict__ h0, const float* __restrict__ c0,
        const float* __restrict__ Wih, const float* __restrict__ Whh,
        const float* __restrict__ bih, const float* __restrict__ bhh,
        float* __restrict__ hs)
{
    __shared__ __align__(16) float4 sWhh4[1024];  // [k][lane] -> gates
    __shared__ __align__(16) float4 sWihP[96];    // [j=0..2][lane] -> gates
    __shared__ __align__(16) float4 sb4[32];
    __shared__ __align__(16) u64 shh[1024];       // [w][lane][pr]
    const int tid = threadIdx.x;

    for (int i = tid; i < 4096; i += 256) {
        int r = i >> 5, k = i & 31;
        ((float*)sWhh4)[(k*32 + (r & 31))*4 + (r >> 5)] = Whh[i];
    }
    for (int i = tid; i < 384; i += 256) {
        int r = i / 3, j = i - r*3;
        ((float*)sWihP)[(j*32 + (r & 31))*4 + (r >> 5)] = Wih[i];
    }
    if (tid < 128) ((float*)sb4)[(tid & 31)*4 + (tid >> 5)] = bih[tid] + bhh[tid];
    __syncthreads();

    const int lane = tid & 31;
    const int w = tid >> 5;
    const int n0 = blockIdx.x * 64 + w * 8;

    float h[8], c[8];
    #pragma unroll
    for (int r = 0; r < 8; r++) { h[r] = h0[(n0+r)*32 + lane]; c[r] = c0[(n0+r)*32 + lane]; }

    const float4 bb = sb4[lane];
    u64 bd[4];
    PACK2(bd[0], bb.x, bb.x); PACK2(bd[1], bb.y, bb.y);
    PACK2(bd[2], bb.z, bb.z); PACK2(bd[3], bb.w, bb.w);

    #pragma unroll 1
    for (int t = 0; t < TT; t++) {
        __syncwarp();
        #pragma unroll
        for (int pr = 0; pr < 4; pr++) {
            u64 hq;
            PACK2(hq, h[2*pr], h[2*pr+1]);
            shh[(w*32 + lane)*4 + pr] = hq;
        }
        __syncwarp();

        u64 ac[16];   // [g*4 + pp]
        #pragma unroll
        for (int g = 0; g < 4; g++) {
            ac[g*4] = bd[g]; ac[g*4+1] = bd[g]; ac[g*4+2] = bd[g]; ac[g*4+3] = bd[g];
        }

        // x part: 3 input features
        const float* xp = x + ((size_t)t*NN + n0) * 3;
        #pragma unroll
        for (int j = 0; j < 3; j++) {
            float4 wj = sWihP[j*32 + lane];
            u64 xq[4];
            #pragma unroll
            for (int pr = 0; pr < 4; pr++)
                PACK2(xq[pr], xp[(2*pr)*3 + j], xp[(2*pr+1)*3 + j]);
            u64 d;
            PACK2(d, wj.x, wj.x);
            FMA2(ac[0],  xq[0], d); FMA2(ac[1],  xq[1], d); FMA2(ac[2],  xq[2], d); FMA2(ac[3],  xq[3], d);
            PACK2(d, wj.y, wj.y);
            FMA2(ac[4],  xq[0], d); FMA2(ac[5],  xq[1], d); FMA2(ac[6],  xq[2], d); FMA2(ac[7],  xq[3], d);
            PACK2(d, wj.z, wj.z);
            FMA2(ac[8],  xq[0], d); FMA2(ac[9],  xq[1], d); FMA2(ac[10], xq[2], d); FMA2(ac[11], xq[3], d);
            PACK2(d, wj.w, wj.w);
            FMA2(ac[12], xq[0], d); FMA2(ac[13], xq[1], d); FMA2(ac[14], xq[2], d); FMA2(ac[15], xq[3], d);
        }

        // h recurrence
        #pragma unroll
        for (int k = 0; k < 32; k++) {
            float4 wh = sWhh4[k*32 + lane];
            ulonglong2 ha = *(const ulonglong2*)&shh[(w*32 + k)*4];
            ulonglong2 hb = *(const ulonglong2*)&shh[(w*32 + k)*4 + 2];
            u64 d;
            PACK2(d, wh.x, wh.x);
            FMA2(ac[0],  ha.x, d); FMA2(ac[1],  ha.y, d); FMA2(ac[2],  hb.x, d); FMA2(ac[3],  hb.y, d);
            PACK2(d, wh.y, wh.y);
            FMA2(ac[4],  ha.x, d); FMA2(ac[5],  ha.y, d); FMA2(ac[6],  hb.x, d); FMA2(ac[7],  hb.y, d);
            PACK2(d, wh.z, wh.z);
            FMA2(ac[8],  ha.x, d); FMA2(ac[9],  ha.y, d); FMA2(ac[10], hb.x, d); FMA2(ac[11], hb.y, d);
            PACK2(d, wh.w, wh.w);
            FMA2(ac[12], ha.x, d); FMA2(ac[13], ha.y, d); FMA2(ac[14], hb.x, d); FMA2(ac[15], hb.y, d);
        }

        #pragma unroll
        for (int pr = 0; pr < 4; pr++) {
            float A0a, A0b, A1a, A1b, A2a, A2b, A3a, A3b;
            UNPACK2(A0a, A0b, ac[0*4 + pr]);
            UNPACK2(A1a, A1b, ac[1*4 + pr]);
            UNPACK2(A2a, A2b, ac[2*4 + pr]);
            UNPACK2(A3a, A3b, ac[3*4 + pr]);
            int r0 = 2*pr, r1 = 2*pr + 1;
            c[r0] = sig_fast(A1a) * c[r0] + sig_fast(A0a) * tanh_fast(A2a);
            h[r0] = sig_fast(A3a) * tanh_fast(c[r0]);
            c[r1] = sig_fast(A1b) * c[r1] + sig_fast(A0b) * tanh_fast(A2b);
            h[r1] = sig_fast(A3b) * tanh_fast(c[r1]);
            hs[((size_t)t*NN + n0 + r0)*32 + lane] = h[r0];
            hs[((size_t)t*NN + n0 + r1)*32 + lane] = h[r1];
        }
    }
}

// ---------------------------------------------------------------------------
// FUSED GAT: layer0 (4 heads) + layer1. Weight-shared matmul loops.
// ---------------------------------------------------------------------------
__global__ void gat_fused_kernel(const float* __restrict__ traj,
        const float* __restrict__ w0, const float* __restrict__ as0,
        const float* __restrict__ ad0, const float* __restrict__ b0,
        const float* __restrict__ w1, const float* __restrict__ as1,
        const float* __restrict__ ad1, const float* __restrict__ b1)
{
    __shared__ __align__(16) float sA[4416];
    __shared__ __align__(16) float sB[4416];
    __shared__ float sS[256], sD[256];
    __shared__ __align__(16) float smean[64], sinv[64];
    __shared__ float srinv[64];
    __shared__ float sas0[64], sad0[64], sas1[32], sad1[32];
    __shared__ __align__(16) float4 sb0v[4];
    __shared__ __align__(16) float4 sb1v[8];

    const int tid = threadIdx.x;
    const int b = blockIdx.x, sIdx = b >> 3, tIdx = b & 7;

    float4* sxA = (float4*)sA;            // x quads [0:512)
    float4* swA = (float4*)(sA + 2048);   // w0 quads
    float4* hpB = (float4*)sB;            // hp0 / x2 quads

    // ---- prologue ----
    {
        const float4* src = (const float4*)(traj + ((size_t)tIdx*NN + sIdx*64) * 32);
        for (int i = tid; i < 512; i += 256) sxA[i] = src[i];
        const float4* wsrc = (const float4*)w0;
        for (int i = tid; i < 512; i += 256) swA[i] = wsrc[i];
        if (tid < 64) { sas0[tid] = as0[tid]; sad0[tid] = ad0[tid]; }
        if (tid < 32) { sas1[tid] = as1[tid]; sad1[tid] = ad1[tid]; }
        if (tid < 4)  sb0v[tid] = ((const float4*)b0)[tid];
        if (tid < 8)  sb1v[tid] = ((const float4*)b1)[tid];
    }
    __syncthreads();

    // ---- layer0 instance-norm stats ----
    {
        int f = tid & 31, g = tid >> 5;
        float s = 0.f, s2 = 0.f;
        #pragma unroll
        for (int i = 0; i < 8; i++) { float v = sA[(g*8+i)*32 + f]; s += v; s2 += v*v; }
        sB[g*32 + f] = s;
        sB[256 + g*32 + f] = s2;
    }
    __syncthreads();
    if (tid < 32) {
        float s = 0.f, s2 = 0.f;
        #pragma unroll
        for (int g = 0; g < 8; g++) { s += sB[g*32 + tid]; s2 += sB[256 + g*32 + tid]; }
        float m = s * (1.0f/64.0f);
        float var = s2 * (1.0f/64.0f) - m*m;
        smean[tid] = m; sinv[tid] = rsqrtf(var + 1e-5f);
    }
    __syncthreads();
    for (int i = tid; i < 512; i += 256) {
        int f4 = i & 7;
        float4 m4 = ((float4*)smean)[f4], i4 = ((float4*)sinv)[f4];
        float4 v = sxA[i];
        v.x = (v.x - m4.x)*i4.x; v.y = (v.y - m4.y)*i4.y;
        v.z = (v.z - m4.z)*i4.z; v.w = (v.w - m4.w)*i4.w;
        sxA[i] = v;
    }
    __syncthreads();

    // ---- hp0 matmul (FMA2, weights shared over 4 p-rows per thread) ----
    {
        int j = tid & 15, hh = j >> 2, o4 = j & 3;
        int p0 = tid >> 4;
        u64 a01[4] = {0,0,0,0}, a23[4] = {0,0,0,0};
        #pragma unroll
        for (int f4 = 0; f4 < 8; f4++) {
            const ulonglong2* wp = (const ulonglong2*)&swA[hh*128 + (f4*4)*4 + o4];
            ulonglong2 wv0 = wp[0], wv1 = wp[4], wv2 = wp[8], wv3 = wp[12];
            #pragma unroll
            for (int r = 0; r < 4; r++) {
                float4 xv = sxA[(p0 + r*16)*8 + f4];
                u64 xd;
                PACK2(xd, xv.x, xv.x); FMA2(a01[r], xd, wv0.x); FMA2(a23[r], xd, wv0.y);
                PACK2(xd, xv.y, xv.y); FMA2(a01[r], xd, wv1.x); FMA2(a23[r], xd, wv1.y);
                PACK2(xd, xv.z, xv.z); FMA2(a01[r], xd, wv2.x); FMA2(a23[r], xd, wv2.y);
                PACK2(xd, xv.w, xv.w); FMA2(a01[r], xd, wv3.x); FMA2(a23[r], xd, wv3.y);
            }
        }
        #pragma unroll
        for (int r = 0; r < 4; r++) {
            u64* dst = (u64*)sB + ((p0 + r*16)*16 + hh*4 + o4)*2;
            dst[0] = a01[r]; dst[1] = a23[r];
        }
    }
    __syncthreads();

    // ---- s[h][p], d[h][p] ----
    {
        int hh = tid >> 6, p = tid & 63;
        float as = 0.f, ad = 0.f;
        #pragma unroll
        for (int o4 = 0; o4 < 4; o4++) {
            float4 v = hpB[p*16 + hh*4 + o4];
            int ob = hh*16 + o4*4;
            as += v.x*sas0[ob] + v.y*sas0[ob+1] + v.z*sas0[ob+2] + v.w*sas0[ob+3];
            ad += v.x*sad0[ob] + v.y*sad0[ob+1] + v.z*sad0[ob+2] + v.w*sad0[ob+3];
        }
        sS[tid] = as; sD[tid] = ad;
    }
    __syncthreads();

    // ---- heads loop ----
    for (int hh = 0; hh < 4; hh++) {
        {
            int p = tid >> 2, q = tid & 3;
            float sp = sS[hh*64 + p];
            float l[16]; float mx = -1e30f;
            #pragma unroll
            for (int mm = 0; mm < 16; mm++) {
                float v = sp + sD[hh*64 + q*16 + mm];
                v = (v > 0.f) ? v : 0.2f*v;
                l[mm] = v; mx = fmaxf(mx, v);
            }
            mx = fmaxf(mx, __shfl_xor_sync(0xffffffffu, mx, 1));
            mx = fmaxf(mx, __shfl_xor_sync(0xffffffffu, mx, 2));
            float sum = 0.f;
            #pragma unroll
            for (int mm = 0; mm < 16; mm++) {
                float e = __expf(l[mm] - mx);
                sA[p*AST + q*16 + mm] = e; sum += e;
            }
            sum += __shfl_xor_sync(0xffffffffu, sum, 1);
            sum += __shfl_xor_sync(0xffffffffu, sum, 2);
            if (q == 0) srinv[p] = 1.0f / sum;
        }
        __syncthreads();
        float4 res;
        {
            int p = tid >> 2, o4 = tid & 3;
            const float* ap = &sA[p*AST];
            const ulonglong2* hp2 = (const ulonglong2*)sB;
            u64 a01 = 0ull, a23 = 0ull;
            #pragma unroll
            for (int m = 0; m < 64; m++) {
                u64 ad; PACK2(ad, ap[m], ap[m]);
                ulonglong2 hv = hp2[m*16 + hh*4 + o4];
                FMA2(a01, ad, hv.x); FMA2(a23, ad, hv.y);
            }
            float4 acc;
            UNPACK2(acc.x, acc.y, a01);
            UNPACK2(acc.z, acc.w, a23);
            float ri = srinv[p];
            float4 bb = sb0v[o4];
            res.x = acc.x*ri + bb.x; res.y = acc.y*ri + bb.y;
            res.z = acc.z*ri + bb.z; res.w = acc.w*ri + bb.w;
            res.x = (res.x > 0.f) ? res.x : (__expf(res.x) - 1.f);
            res.y = (res.y > 0.f) ? res.y : (__expf(res.y) - 1.f);
            res.z = (res.z > 0.f) ? res.z : (__expf(res.z) - 1.f);
            res.w = (res.w > 0.f) ? res.w : (__expf(res.w) - 1.f);
        }
        __syncthreads();
        {
            int p = tid >> 2, o4 = tid & 3;
            hpB[p*16 + hh*4 + o4] = res;
        }
        __syncthreads();
    }
    // sB now holds x2[64][64]

    // ---- layer1 instance-norm stats ----
    {
        int f = tid & 63, g = tid >> 6;
        float s = 0.f, s2 = 0.f;
        #pragma unroll
        for (int i = 0; i < 16; i++) { float v = sB[(g*16+i)*64 + f]; s += v; s2 += v*v; }
        sA[g*64 + f] = s;
        sA[256 + g*64 + f] = s2;
    }
    __syncthreads();
    if (tid < 64) {
        float s = 0.f, s2 = 0.f;
        #pragma unroll
        for (int g = 0; g < 4; g++) { s += sA[g*64 + tid]; s2 += sA[256 + g*64 + tid]; }
        float m = s * (1.0f/64.0f);
        float var = s2 * (1.0f/64.0f) - m*m;
        smean[tid] = m; sinv[tid] = rsqrtf(var + 1e-5f);
    }
    __syncthreads();
    for (int i = tid; i < 1024; i += 256) {
        int f4 = i & 15;
        float4 m4 = ((float4*)smean)[f4], i4 = ((float4*)sinv)[f4];
        float4 v = hpB[i];
        v.x = (v.x - m4.x)*i4.x; v.y = (v.y - m4.y)*i4.y;
        v.z = (v.z - m4.z)*i4.z; v.w = (v.w - m4.w)*i4.w;
        hpB[i] = v;
    }
    for (int i = tid; i < 512; i += 256) ((float4*)sA)[i] = ((const float4*)w1)[i];
    __syncthreads();

    // ---- hp1 matmul (FMA2, weights shared over 2 p-rows) ----
    {
        float4* sw1q = (float4*)sA;
        int o4 = tid & 7, p0 = tid >> 3;
        u64 a01[2] = {0,0}, a23[2] = {0,0};
        #pragma unroll
        for (int f4 = 0; f4 < 16; f4++) {
            const ulonglong2* wp = (const ulonglong2*)&sw1q[(f4*4)*8 + o4];
            ulonglong2 wv0 = wp[0], wv1 = wp[8], wv2 = wp[16], wv3 = wp[24];
            #pragma unroll
            for (int r = 0; r < 2; r++) {
                float4 xv = hpB[(p0 + r*32)*16 + f4];
                u64 xd;
                PACK2(xd, xv.x, xv.x); FMA2(a01[r], xd, wv0.x); FMA2(a23[r], xd, wv0.y);
                PACK2(xd, xv.y, xv.y); FMA2(a01[r], xd, wv1.x); FMA2(a23[r], xd, wv1.y);
                PACK2(xd, xv.z, xv.z); FMA2(a01[r], xd, wv2.x); FMA2(a23[r], xd, wv2.y);
                PACK2(xd, xv.w, xv.w); FMA2(a01[r], xd, wv3.x); FMA2(a23[r], xd, wv3.y);
            }
        }
        #pragma unroll
        for (int r = 0; r < 2; r++) {
            u64* dst = (u64*)(sA + 2048) + ((p0 + r*32)*8 + o4)*2;
            dst[0] = a01[r]; dst[1] = a23[r];
        }
    }
    __syncthreads();

    // ---- s1/d1 ----
    if (tid < 64) {
        int p = tid;
        const float4* hp4 = (const float4*)(sA + 2048);
        float as = 0.f, ad = 0.f;
        #pragma unroll
        for (int o4 = 0; o4 < 8; o4++) {
            float4 v = hp4[p*8 + o4];
            as += v.x*sas1[o4*4] + v.y*sas1[o4*4+1] + v.z*sas1[o4*4+2] + v.w*sas1[o4*4+3];
            ad += v.x*sad1[o4*4] + v.y*sad1[o4*4+1] + v.z*sad1[o4*4+2] + v.w*sad1[o4*4+3];
        }
        sS[p] = as; sD[p] = ad;
    }
    __syncthreads();

    // ---- softmax2 into sB ----
    {
        int p = tid >> 2, q = tid & 3;
        float sp = sS[p];
        float l[16]; float mx = -1e30f;
        #pragma unroll
        for (int mm = 0; mm < 16; mm++) {
            float v = sp + sD[q*16 + mm];
            v = (v > 0.f) ? v : 0.2f*v;
            l[mm] = v; mx = fmaxf(mx, v);
        }
        mx = fmaxf(mx, __shfl_xor_sync(0xffffffffu, mx, 1));
        mx = fmaxf(mx, __shfl_xor_sync(0xffffffffu, mx, 2));
        float sum = 0.f;
        #pragma unroll
        for (int mm = 0; mm < 16; mm++) {
            float e = __expf(l[mm] - mx);
            sB[p*AST + q*16 + mm] = e; sum += e;
        }
        sum += __shfl_xor_sync(0xffffffffu, sum, 1);
        sum += __shfl_xor_sync(0xffffffffu, sum, 2);
        if (q == 0) srinv[p] = 1.0f / sum;
    }
    __syncthreads();

    // ---- apply2 (hv shared over 2 p-rows) -> g_graph_in ----
    {
        int o4 = tid & 7, p0 = tid >> 3;
        const float* ap0 = &sB[p0*AST];
        const float* ap1 = &sB[(p0+32)*AST];
        const ulonglong2* hp2 = (const ulonglong2*)(sA + 2048);
        u64 a01_0 = 0ull, a23_0 = 0ull, a01_1 = 0ull, a23_1 = 0ull;
        #pragma unroll
        for (int m = 0; m < 64; m++) {
            ulonglong2 hv = hp2[m*8 + o4];
            u64 ad;
            PACK2(ad, ap0[m], ap0[m]); FMA2(a01_0, ad, hv.x); FMA2(a23_0, ad, hv.y);
            PACK2(ad, ap1[m], ap1[m]); FMA2(a01_1, ad, hv.x); FMA2(a23_1, ad, hv.y);
        }
        float4 bb = sb1v[o4];
        {
            float4 acc;
            UNPACK2(acc.x, acc.y, a01_0);
            UNPACK2(acc.z, acc.w, a23_0);
            float ri = srinv[p0];
            float4 res;
            res.x = acc.x*ri + bb.x; res.y = acc.y*ri + bb.y;
            res.z = acc.z*ri + bb.z; res.w = acc.w*ri + bb.w;
            ((float4*)g_graph_in)[((size_t)tIdx*NN + sIdx*64 + p0)*8 + o4] = res;
        }
        {
            float4 acc;
            UNPACK2(acc.x, acc.y, a01_1);
            UNPACK2(acc.z, acc.w, a23_1);
            float ri = srinv[p0 + 32];
            float4 res;
            res.x = acc.x*ri + bb.x; res.y = acc.y*ri + bb.y;
            res.z = acc.z*ri + bb.z; res.w = acc.w*ri + bb.w;
            ((float4*)g_graph_in)[((size_t)tIdx*NN + sIdx*64 + p0 + 32)*8 + o4] = res;
        }
    }
}

// ---------------------------------------------------------------------------
// LSTM graph (fused x+h): input 32, hidden 32. Warp = 8 peds (4 f32x2 pairs).
// (unchanged — measured 104 us)
// ---------------------------------------------------------------------------
__global__ void lstm_graph_kernel(
        const float* __restrict__ h0, const float* __restrict__ c0,
        const float* __restrict__ Wih, const float* __restrict__ Whh,
        const float* __restrict__ bih, const float* __restrict__ bhh,
        float* __restrict__ hs)
{
    __shared__ __align__(16) float4 sWih4[1024];  // [k][lane] -> gates
    __shared__ __align__(16) float4 sWhh4[1024];
    __shared__ __align__(16) float4 sb4[32];
    __shared__ __align__(16) u64 shx[1024];       // [w][k][pp]
    __shared__ __align__(16) u64 shh[1024];
    const int tid = threadIdx.x;

    for (int i = tid; i < 4096; i += 256) {
        int r = i >> 5, k = i & 31;
        int idx = (k*32 + (r & 31))*4 + (r >> 5);
        ((float*)sWih4)[idx] = Wih[i];
        ((float*)sWhh4)[idx] = Whh[i];
    }
    if (tid < 128) ((float*)sb4)[(tid & 31)*4 + (tid >> 5)] = bih[tid] + bhh[tid];
    __syncthreads();

    const int lane = tid & 31;
    const int w = tid >> 5;
    const int n0 = blockIdx.x * 64 + w * 8;

    float h[8], c[8];
    #pragma unroll
    for (int r = 0; r < 8; r++) { h[r] = h0[(n0+r)*32 + lane]; c[r] = c0[(n0+r)*32 + lane]; }

    const float4 bb = sb4[lane];
    u64 bd[4];
    PACK2(bd[0], bb.x, bb.x); PACK2(bd[1], bb.y, bb.y);
    PACK2(bd[2], bb.z, bb.z); PACK2(bd[3], bb.w, bb.w);

    #pragma unroll 1
    for (int t = 0; t < TT; t++) {
        __syncwarp();
        #pragma unroll
        for (int pr = 0; pr < 4; pr++) {
            float x0 = g_graph_in[((size_t)t*NN + n0 + 2*pr    )*32 + lane];
            float x1 = g_graph_in[((size_t)t*NN + n0 + 2*pr + 1)*32 + lane];
            u64 xq, hq;
            PACK2(xq, x0, x1);
            PACK2(hq, h[2*pr], h[2*pr+1]);
            shx[(w*32 + lane)*4 + pr] = xq;
            shh[(w*32 + lane)*4 + pr] = hq;
        }
        __syncwarp();

        u64 ac[16];   // [g*4 + pp]
        #pragma unroll
        for (int g = 0; g < 4; g++) {
            ac[g*4] = bd[g]; ac[g*4+1] = bd[g]; ac[g*4+2] = bd[g]; ac[g*4+3] = bd[g];
        }

        #pragma unroll
        for (int k = 0; k < 32; k++) {
            float4 wi = sWih4[k*32 + lane];
            float4 wh = sWhh4[k*32 + lane];
            ulonglong2 xa = *(const ulonglong2*)&shx[(w*32 + k)*4];
            ulonglong2 xb = *(const ulonglong2*)&shx[(w*32 + k)*4 + 2];
            ulonglong2 ha = *(const ulonglong2*)&shh[(w*32 + k)*4];
            ulonglong2 hb = *(const ulonglong2*)&shh[(w*32 + k)*4 + 2];
            u64 d;
            PACK2(d, wi.x, wi.x);
            FMA2(ac[0],  xa.x, d); FMA2(ac[1],  xa.y, d); FMA2(ac[2],  xb.x, d); FMA2(ac[3],  xb.y, d);
            PACK2(d, wi.y, wi.y);
            FMA2(ac[4],  xa.x, d); FMA2(ac[5],  xa.y, d); FMA2(ac[6],  xb.x, d); FMA2(ac[7],  xb.y, d);
            PACK2(d, wi.z, wi.z);
            FMA2(ac[8],  xa.x, d); FMA2(ac[9],  xa.y, d); FMA2(ac[10], xb.x, d); FMA2(ac[11], xb.y, d);
            PACK2(d, wi.w, wi.w);
            FMA2(ac[12], xa.x, d); FMA2(ac[13], xa.y, d); FMA2(ac[14], xb.x, d); FMA2(ac[15], xb.y, d);
            PACK2(d, wh.x, wh.x);
            FMA2(ac[0],  ha.x, d); FMA2(ac[1],  ha.y, d); FMA2(ac[2],  hb.x, d); FMA2(ac[3],  hb.y, d);
            PACK2(d, wh.y, wh.y);
            FMA2(ac[4],  ha.x, d); FMA2(ac[5],  ha.y, d); FMA2(ac[6],  hb.x, d); FMA2(ac[7],  hb.y, d);
            PACK2(d, wh.z, wh.z);
            FMA2(ac[8],  ha.x, d); FMA2(ac[9],  ha.y, d); FMA2(ac[10], hb.x, d); FMA2(ac[11], hb.y, d);
            PACK2(d, wh.w, wh.w);
            FMA2(ac[12], ha.x, d); FMA2(ac[13], ha.y, d); FMA2(ac[14], hb.x, d); FMA2(ac[15], hb.y, d);
        }

        #pragma unroll
        for (int pr = 0; pr < 4; pr++) {
            float A0a, A0b, A1a, A1b, A2a, A2b, A3a, A3b;
            UNPACK2(A0a, A0b, ac[0*4 + pr]);
            UNPACK2(A1a, A1b, ac[1*4 + pr]);
            UNPACK2(A2a, A2b, ac[2*4 + pr]);
            UNPACK2(A3a, A3b, ac[3*4 + pr]);
            int r0 = 2*pr, r1 = 2*pr + 1;
            c[r0] = sig_fast(A1a) * c[r0] + sig_fast(A0a) * tanh_fast(A2a);
            h[r0] = sig_fast(A3a) * tanh_fast(c[r0]);
            c[r1] = sig_fast(A1b) * c[r1] + sig_fast(A0b) * tanh_fast(A2b);
            h[r1] = sig_fast(A3b) * tanh_fast(c[r1]);
            hs[((size_t)t*NN + n0 + r0)*32 + lane] = h[r0];
            hs[((size_t)t*NN + n0 + r1)*32 + lane] = h[r1];
        }
    }
}

// ---------------------------------------------------------------------------
// Concat (float4): encoded[n] = [traj_hs[7,n] | graph_hs[7,n] | z[n/64]]
// ---------------------------------------------------------------------------
__global__ void concat_kernel(const float* __restrict__ z,
        const float* __restrict__ traj, const float* __restrict__ graph,
        float* __restrict__ out)
{
    int idx = blockIdx.x * blockDim.x + threadIdx.x;
    if (idx >= NN*18) return;
    int n = idx / 18, j = idx - n*18;
    float4 v;
    if (j < 8)       v = ((const float4*)traj)[((size_t)7*NN + n)*8 + j];
    else if (j < 16) v = ((const float4*)graph)[((size_t)7*NN + n)*8 + (j - 8)];
    else             v = ((const float4*)z)[(n >> 6)*2 + (j - 16)];
    ((float4*)out)[idx] = v;
}

extern "C" void kernel_launch(void* const* d_in, const int* in_sizes, int n_in,
                              void* d_out, int out_size) {
    const float* obs  = (const float*)d_in[0];
    const float* h0t  = (const float*)d_in[1];
    const float* c0t  = (const float*)d_in[2];
    const float* h0g  = (const float*)d_in[3];
    const float* c0g  = (const float*)d_in[4];
    const float* z    = (const float*)d_in[5];
    const float* WihT = (const float*)d_in[6];
    const float* WhhT = (const float*)d_in[7];
    const float* bihT = (const float*)d_in[8];
    const float* bhhT = (const float*)d_in[9];
    const float* WihG = (const float*)d_in[10];
    const float* WhhG = (const float*)d_in[11];
    const float* bihG = (const float*)d_in[12];
    const float* bhhG = (const float*)d_in[13];
    const float* w0   = (const float*)d_in[14];
    const float* as0  = (const float*)d_in[15];
    const float* ad0  = (const float*)d_in[16];
    const float* b0   = (const float*)d_in[17];
    const float* w1   = (const float*)d_in[18];
    const float* as1  = (const float*)d_in[19];
    const float* ad1  = (const float*)d_in[20];
    const float* b1   = (const float*)d_in[21];
    float* out = (float*)d_out;

    float* traj_hs;
    float* graph_hs;
    if (out_size >= ENC_ELEMS + 2*SEQ_ELEMS) {
        graph_hs = out + ENC_ELEMS;
        traj_hs  = out + ENC_ELEMS + SEQ_ELEMS;
    } else {
        void* pt = nullptr; void* pg = nullptr;
        cudaGetSymbolAddress(&pt, g_traj_fb);
        cudaGetSymbolAddress(&pg, g_graph_fb);
        traj_hs  = (float*)pt;
        graph_hs = (float*)pg;
    }

    lstm_traj_kernel<<<NN/64, 256>>>(obs, h0t, c0t, WihT, WhhT, bihT, bhhT, traj_hs);
    gat_fused_kernel<<<SS*TT, 256>>>(traj_hs, w0, as0, ad0, b0, w1, as1, ad1, b1);
    lstm_graph_kernel<<<NN/64, 256>>>(h0g, c0g, WihG, WhhG, bihG, bhhG, graph_hs);
    concat_kernel<<<(NN*18 + 255)/256, 256>>>(z, traj_hs, graph_hs, out);
}

// round 16
// speedup vs baseline: 1.5060x; 1.0004x over previous
#include <cuda_runtime.h>
#include <math.h>

#define SS 512
#define PP 64
#define TT 8
#define NN (SS*PP)            // 32768

#define ENC_ELEMS (NN*72)     // 2359296
#define SEQ_ELEMS (TT*NN*32)  // 8388608

#define AST 68                // padded attention row stride (floats)

typedef unsigned long long u64;

__device__ float g_graph_in[SEQ_ELEMS];        // GAT output -> graph LSTM input
__device__ float g_traj_fb[SEQ_ELEMS];
__device__ float g_graph_fb[SEQ_ELEMS];

__device__ __forceinline__ float tanh_fast(float x){
    float y; asm("tanh.approx.f32 %0, %1;" : "=f"(y) : "f"(x)); return y;
}
__device__ __forceinline__ float sig_fast(float x){
    return 0.5f * tanh_fast(0.5f * x) + 0.5f;
}

#define FMA2(d, a, b) asm("fma.rn.f32x2 %0, %1, %2, %0;" : "+l"(d) : "l"(a), "l"(b))
#define PACK2(d, lo, hi) asm("mov.b64 %0, {%1, %2};" : "=l"(d) : "f"(lo), "f"(hi))
#define UNPACK2(lo, hi, s) asm("mov.b64 {%0, %1}, %2;" : "=f"(lo), "=f"(hi) : "l"(s))

// ---------------------------------------------------------------------------
// LSTM traj: input 3, hidden 32, T=8. Warp = 8 peds (4 f32x2 pairs).
// At t=7 also writes encoded[n][0:32].
// ---------------------------------------------------------------------------
__global__ void lstm_traj_kernel(const float* __restrict__ x,
        const float* __restrict__ h0, const float* __restrict__ c0,
        const float* __restrict__ Wih, const float* __restrict__ Whh,
        const float* __restrict__ bih, const float* __restrict__ bhh,
        float* __restrict__ hs, float* __restrict__ enc)
{
    __shared__ __align__(16) float4 sWhh4[1024];  // [k][lane] -> gates
    __shared__ __align__(16) float4 sWihP[96];    // [j=0..2][lane] -> gates
    __shared__ __align__(16) float4 sb4[32];
    __shared__ __align__(16) u64 shh[1024];       // [w][lane][pr]
    const int tid = threadIdx.x;

    for (int i = tid; i < 4096; i += 256) {
        int r = i >> 5, k = i & 31;
        ((float*)sWhh4)[(k*32 + (r & 31))*4 + (r >> 5)] = Whh[i];
    }
    for (int i = tid; i < 384; i += 256) {
        int r = i / 3, j = i - r*3;
        ((float*)sWihP)[(j*32 + (r & 31))*4 + (r >> 5)] = Wih[i];
    }
    if (tid < 128) ((float*)sb4)[(tid & 31)*4 + (tid >> 5)] = bih[tid] + bhh[tid];
    __syncthreads();

    const int lane = tid & 31;
    const int w = tid >> 5;
    const int n0 = blockIdx.x * 64 + w * 8;

    float h[8], c[8];
    #pragma unroll
    for (int r = 0; r < 8; r++) { h[r] = h0[(n0+r)*32 + lane]; c[r] = c0[(n0+r)*32 + lane]; }

    const float4 bb = sb4[lane];
    u64 bd[4];
    PACK2(bd[0], bb.x, bb.x); PACK2(bd[1], bb.y, bb.y);
    PACK2(bd[2], bb.z, bb.z); PACK2(bd[3], bb.w, bb.w);

    #pragma unroll 1
    for (int t = 0; t < TT; t++) {
        __syncwarp();
        #pragma unroll
        for (int pr = 0; pr < 4; pr++) {
            u64 hq;
            PACK2(hq, h[2*pr], h[2*pr+1]);
            shh[(w*32 + lane)*4 + pr] = hq;
        }
        __syncwarp();

        u64 ac[16];   // [g*4 + pp]
        #pragma unroll
        for (int g = 0; g < 4; g++) {
            ac[g*4] = bd[g]; ac[g*4+1] = bd[g]; ac[g*4+2] = bd[g]; ac[g*4+3] = bd[g];
        }

        const float* xp = x + ((size_t)t*NN + n0) * 3;
        #pragma unroll
        for (int j = 0; j < 3; j++) {
            float4 wj = sWihP[j*32 + lane];
            u64 xq[4];
            #pragma unroll
            for (int pr = 0; pr < 4; pr++)
                PACK2(xq[pr], xp[(2*pr)*3 + j], xp[(2*pr+1)*3 + j]);
            u64 d;
            PACK2(d, wj.x, wj.x);
            FMA2(ac[0],  xq[0], d); FMA2(ac[1],  xq[1], d); FMA2(ac[2],  xq[2], d); FMA2(ac[3],  xq[3], d);
            PACK2(d, wj.y, wj.y);
            FMA2(ac[4],  xq[0], d); FMA2(ac[5],  xq[1], d); FMA2(ac[6],  xq[2], d); FMA2(ac[7],  xq[3], d);
            PACK2(d, wj.z, wj.z);
            FMA2(ac[8],  xq[0], d); FMA2(ac[9],  xq[1], d); FMA2(ac[10], xq[2], d); FMA2(ac[11], xq[3], d);
            PACK2(d, wj.w, wj.w);
            FMA2(ac[12], xq[0], d); FMA2(ac[13], xq[1], d); FMA2(ac[14], xq[2], d); FMA2(ac[15], xq[3], d);
        }

        #pragma unroll
        for (int k = 0; k < 32; k++) {
            float4 wh = sWhh4[k*32 + lane];
            ulonglong2 ha = *(const ulonglong2*)&shh[(w*32 + k)*4];
            ulonglong2 hb = *(const ulonglong2*)&shh[(w*32 + k)*4 + 2];
            u64 d;
            PACK2(d, wh.x, wh.x);
            FMA2(ac[0],  ha.x, d); FMA2(ac[1],  ha.y, d); FMA2(ac[2],  hb.x, d); FMA2(ac[3],  hb.y, d);
            PACK2(d, wh.y, wh.y);
            FMA2(ac[4],  ha.x, d); FMA2(ac[5],  ha.y, d); FMA2(ac[6],  hb.x, d); FMA2(ac[7],  hb.y, d);
            PACK2(d, wh.z, wh.z);
            FMA2(ac[8],  ha.x, d); FMA2(ac[9],  ha.y, d); FMA2(ac[10], hb.x, d); FMA2(ac[11], hb.y, d);
            PACK2(d, wh.w, wh.w);
            FMA2(ac[12], ha.x, d); FMA2(ac[13], ha.y, d); FMA2(ac[14], hb.x, d); FMA2(ac[15], hb.y, d);
        }

        #pragma unroll
        for (int pr = 0; pr < 4; pr++) {
            float A0a, A0b, A1a, A1b, A2a, A2b, A3a, A3b;
            UNPACK2(A0a, A0b, ac[0*4 + pr]);
            UNPACK2(A1a, A1b, ac[1*4 + pr]);
            UNPACK2(A2a, A2b, ac[2*4 + pr]);
            UNPACK2(A3a, A3b, ac[3*4 + pr]);
            int r0 = 2*pr, r1 = 2*pr + 1;
            c[r0] = sig_fast(A1a) * c[r0] + sig_fast(A0a) * tanh_fast(A2a);
            h[r0] = sig_fast(A3a) * tanh_fast(c[r0]);
            c[r1] = sig_fast(A1b) * c[r1] + sig_fast(A0b) * tanh_fast(A2b);
            h[r1] = sig_fast(A3b) * tanh_fast(c[r1]);
            hs[((size_t)t*NN + n0 + r0)*32 + lane] = h[r0];
            hs[((size_t)t*NN + n0 + r1)*32 + lane] = h[r1];
        }
        if (t == TT-1) {
            #pragma unroll
            for (int r = 0; r < 8; r++)
                enc[(size_t)(n0 + r)*72 + lane] = h[r];
        }
    }
}

// ---------------------------------------------------------------------------
// FUSED GAT: layer0 (4 heads, x2 held in regs) + layer1.
// ---------------------------------------------------------------------------
__global__ void gat_fused_kernel(const float* __restrict__ traj,
        const float* __restrict__ w0, const float* __restrict__ as0,
        const float* __restrict__ ad0, const float* __restrict__ b0,
        const float* __restrict__ w1, const float* __restrict__ as1,
        const float* __restrict__ ad1, const float* __restrict__ b1)
{
    __shared__ __align__(16) float sA[4416];
    __shared__ __align__(16) float sB[4416];
    __shared__ float sS[256], sD[256];
    __shared__ __align__(16) float smean[64], sinv[64];
    __shared__ float srinv[64];
    __shared__ float sas0[64], sad0[64], sas1[32], sad1[32];
    __shared__ __align__(16) float4 sb0v[4];
    __shared__ __align__(16) float4 sb1v[8];

    const int tid = threadIdx.x;
    const int b = blockIdx.x, sIdx = b >> 3, tIdx = b & 7;

    float4* sxA = (float4*)sA;            // x quads [0:512)
    float4* swA = (float4*)(sA + 2048);   // w0 quads
    float4* hpB = (float4*)sB;            // hp0 / x2 quads

    // ---- prologue ----
    {
        const float4* src = (const float4*)(traj + ((size_t)tIdx*NN + sIdx*64) * 32);
        for (int i = tid; i < 512; i += 256) sxA[i] = src[i];
        const float4* wsrc = (const float4*)w0;
        for (int i = tid; i < 512; i += 256) swA[i] = wsrc[i];
        if (tid < 64) { sas0[tid] = as0[tid]; sad0[tid] = ad0[tid]; }
        if (tid < 32) { sas1[tid] = as1[tid]; sad1[tid] = ad1[tid]; }
        if (tid < 4)  sb0v[tid] = ((const float4*)b0)[tid];
        if (tid < 8)  sb1v[tid] = ((const float4*)b1)[tid];
    }
    __syncthreads();

    // ---- layer0 instance-norm stats ----
    {
        int f = tid & 31, g = tid >> 5;
        float s = 0.f, s2 = 0.f;
        #pragma unroll
        for (int i = 0; i < 8; i++) { float v = sA[(g*8+i)*32 + f]; s += v; s2 += v*v; }
        sB[g*32 + f] = s;
        sB[256 + g*32 + f] = s2;
    }
    __syncthreads();
    if (tid < 32) {
        float s = 0.f, s2 = 0.f;
        #pragma unroll
        for (int g = 0; g < 8; g++) { s += sB[g*32 + tid]; s2 += sB[256 + g*32 + tid]; }
        float m = s * (1.0f/64.0f);
        float var = s2 * (1.0f/64.0f) - m*m;
        smean[tid] = m; sinv[tid] = rsqrtf(var + 1e-5f);
    }
    __syncthreads();
    for (int i = tid; i < 512; i += 256) {
        int f4 = i & 7;
        float4 m4 = ((float4*)smean)[f4], i4 = ((float4*)sinv)[f4];
        float4 v = sxA[i];
        v.x = (v.x - m4.x)*i4.x; v.y = (v.y - m4.y)*i4.y;
        v.z = (v.z - m4.z)*i4.z; v.w = (v.w - m4.w)*i4.w;
        sxA[i] = v;
    }
    __syncthreads();

    // ---- hp0 matmul (FMA2, weights shared over 4 p-rows per thread) ----
    {
        int j = tid & 15, hh = j >> 2, o4 = j & 3;
        int p0 = tid >> 4;
        u64 a01[4] = {0,0,0,0}, a23[4] = {0,0,0,0};
        #pragma unroll
        for (int f4 = 0; f4 < 8; f4++) {
            const ulonglong2* wp = (const ulonglong2*)&swA[hh*128 + (f4*4)*4 + o4];
            ulonglong2 wv0 = wp[0], wv1 = wp[4], wv2 = wp[8], wv3 = wp[12];
            #pragma unroll
            for (int r = 0; r < 4; r++) {
                float4 xv = sxA[(p0 + r*16)*8 + f4];
                u64 xd;
                PACK2(xd, xv.x, xv.x); FMA2(a01[r], xd, wv0.x); FMA2(a23[r], xd, wv0.y);
                PACK2(xd, xv.y, xv.y); FMA2(a01[r], xd, wv1.x); FMA2(a23[r], xd, wv1.y);
                PACK2(xd, xv.z, xv.z); FMA2(a01[r], xd, wv2.x); FMA2(a23[r], xd, wv2.y);
                PACK2(xd, xv.w, xv.w); FMA2(a01[r], xd, wv3.x); FMA2(a23[r], xd, wv3.y);
            }
        }
        #pragma unroll
        for (int r = 0; r < 4; r++) {
            u64* dst = (u64*)sB + ((p0 + r*16)*16 + hh*4 + o4)*2;
            dst[0] = a01[r]; dst[1] = a23[r];
        }
    }
    __syncthreads();

    // ---- s[h][p], d[h][p] ----
    {
        int hh = tid >> 6, p = tid & 63;
        float as = 0.f, ad = 0.f;
        #pragma unroll
        for (int o4 = 0; o4 < 4; o4++) {
            float4 v = hpB[p*16 + hh*4 + o4];
            int ob = hh*16 + o4*4;
            as += v.x*sas0[ob] + v.y*sas0[ob+1] + v.z*sas0[ob+2] + v.w*sas0[ob+3];
            ad += v.x*sad0[ob] + v.y*sad0[ob+1] + v.z*sad0[ob+2] + v.w*sad0[ob+3];
        }
        sS[tid] = as; sD[tid] = ad;
    }
    __syncthreads();

    // ---- heads loop: x2 results held in registers ----
    float4 res[4];
    for (int hh = 0; hh < 4; hh++) {
        {
            int p = tid >> 2, q = tid & 3;
            float sp = sS[hh*64 + p];
            float l[16]; float mx = -1e30f;
            #pragma unroll
            for (int mm = 0; mm < 16; mm++) {
                float v = sp + sD[hh*64 + q*16 + mm];
                v = (v > 0.f) ? v : 0.2f*v;
                l[mm] = v; mx = fmaxf(mx, v);
            }
            mx = fmaxf(mx, __shfl_xor_sync(0xffffffffu, mx, 1));
            mx = fmaxf(mx, __shfl_xor_sync(0xffffffffu, mx, 2));
            float sum = 0.f;
            #pragma unroll
            for (int mm = 0; mm < 16; mm++) {
                float e = __expf(l[mm] - mx);
                sA[p*AST + q*16 + mm] = e; sum += e;
            }
            sum += __shfl_xor_sync(0xffffffffu, sum, 1);
            sum += __shfl_xor_sync(0xffffffffu, sum, 2);
            if (q == 0) srinv[p] = 1.0f / sum;
        }
        __syncthreads();
        {
            int p = tid >> 2, o4 = tid & 3;
            const float* ap = &sA[p*AST];
            const ulonglong2* hp2 = (const ulonglong2*)sB;
            u64 a01 = 0ull, a23 = 0ull;
            #pragma unroll
            for (int m = 0; m < 64; m++) {
                u64 ad; PACK2(ad, ap[m], ap[m]);
                ulonglong2 hv = hp2[m*16 + hh*4 + o4];
                FMA2(a01, ad, hv.x); FMA2(a23, ad, hv.y);
            }
            float4 acc;
            UNPACK2(acc.x, acc.y, a01);
            UNPACK2(acc.z, acc.w, a23);
            float ri = srinv[p];
            float4 bb = sb0v[o4];
            float4 r;
            r.x = acc.x*ri + bb.x; r.y = acc.y*ri + bb.y;
            r.z = acc.z*ri + bb.z; r.w = acc.w*ri + bb.w;
            r.x = (r.x > 0.f) ? r.x : (__expf(r.x) - 1.f);
            r.y = (r.y > 0.f) ? r.y : (__expf(r.y) - 1.f);
            r.z = (r.z > 0.f) ? r.z : (__expf(r.z) - 1.f);
            r.w = (r.w > 0.f) ? r.w : (__expf(r.w) - 1.f);
            res[hh] = r;
        }
        __syncthreads();   // apply reads of sA/sB done before next softmax / final write
    }
    // write x2 (all heads) over hp region
    {
        int p = tid >> 2, o4 = tid & 3;
        #pragma unroll
        for (int hh = 0; hh < 4; hh++)
            hpB[p*16 + hh*4 + o4] = res[hh];
    }
    __syncthreads();
    // sB now holds x2[64][64]

    // ---- layer1 instance-norm stats ----
    {
        int f = tid & 63, g = tid >> 6;
        float s = 0.f, s2 = 0.f;
        #pragma unroll
        for (int i = 0; i < 16; i++) { float v = sB[(g*16+i)*64 + f]; s += v; s2 += v*v; }
        sA[g*64 + f] = s;
        sA[256 + g*64 + f] = s2;
    }
    __syncthreads();
    if (tid < 64) {
        float s = 0.f, s2 = 0.f;
        #pragma unroll
        for (int g = 0; g < 4; g++) { s += sA[g*64 + tid]; s2 += sA[256 + g*64 + tid]; }
        float m = s * (1.0f/64.0f);
        float var = s2 * (1.0f/64.0f) - m*m;
        smean[tid] = m; sinv[tid] = rsqrtf(var + 1e-5f);
    }
    __syncthreads();
    for (int i = tid; i < 1024; i += 256) {
        int f4 = i & 15;
        float4 m4 = ((float4*)smean)[f4], i4 = ((float4*)sinv)[f4];
        float4 v = hpB[i];
        v.x = (v.x - m4.x)*i4.x; v.y = (v.y - m4.y)*i4.y;
        v.z = (v.z - m4.z)*i4.z; v.w = (v.w - m4.w)*i4.w;
        hpB[i] = v;
    }
    for (int i = tid; i < 512; i += 256) ((float4*)sA)[i] = ((const float4*)w1)[i];
    __syncthreads();

    // ---- hp1 matmul (FMA2, weights shared over 2 p-rows) ----
    {
        float4* sw1q = (float4*)sA;
        int o4 = tid & 7, p0 = tid >> 3;
        u64 a01[2] = {0,0}, a23[2] = {0,0};
        #pragma unroll
        for (int f4 = 0; f4 < 16; f4++) {
            const ulonglong2* wp = (const ulonglong2*)&sw1q[(f4*4)*8 + o4];
            ulonglong2 wv0 = wp[0], wv1 = wp[8], wv2 = wp[16], wv3 = wp[24];
            #pragma unroll
            for (int r = 0; r < 2; r++) {
                float4 xv = hpB[(p0 + r*32)*16 + f4];
                u64 xd;
                PACK2(xd, xv.x, xv.x); FMA2(a01[r], xd, wv0.x); FMA2(a23[r], xd, wv0.y);
                PACK2(xd, xv.y, xv.y); FMA2(a01[r], xd, wv1.x); FMA2(a23[r], xd, wv1.y);
                PACK2(xd, xv.z, xv.z); FMA2(a01[r], xd, wv2.x); FMA2(a23[r], xd, wv2.y);
                PACK2(xd, xv.w, xv.w); FMA2(a01[r], xd, wv3.x); FMA2(a23[r], xd, wv3.y);
            }
        }
        #pragma unroll
        for (int r = 0; r < 2; r++) {
            u64* dst = (u64*)(sA + 2048) + ((p0 + r*32)*8 + o4)*2;
            dst[0] = a01[r]; dst[1] = a23[r];
        }
    }
    __syncthreads();

    // ---- s1/d1 ----
    if (tid < 64) {
        int p = tid;
        const float4* hp4 = (const float4*)(sA + 2048);
        float as = 0.f, ad = 0.f;
        #pragma unroll
        for (int o4 = 0; o4 < 8; o4++) {
            float4 v = hp4[p*8 + o4];
            as += v.x*sas1[o4*4] + v.y*sas1[o4*4+1] + v.z*sas1[o4*4+2] + v.w*sas1[o4*4+3];
            ad += v.x*sad1[o4*4] + v.y*sad1[o4*4+1] + v.z*sad1[o4*4+2] + v.w*sad1[o4*4+3];
        }
        sS[p] = as; sD[p] = ad;
    }
    __syncthreads();

    // ---- softmax2 into sB ----
    {
        int p = tid >> 2, q = tid & 3;
        float sp = sS[p];
        float l[16]; float mx = -1e30f;
        #pragma unroll
        for (int mm = 0; mm < 16; mm++) {
            float v = sp + sD[q*16 + mm];
            v = (v > 0.f) ? v : 0.2f*v;
            l[mm] = v; mx = fmaxf(mx, v);
        }
        mx = fmaxf(mx, __shfl_xor_sync(0xffffffffu, mx, 1));
        mx = fmaxf(mx, __shfl_xor_sync(0xffffffffu, mx, 2));
        float sum = 0.f;
        #pragma unroll
        for (int mm = 0; mm < 16; mm++) {
            float e = __expf(l[mm] - mx);
            sB[p*AST + q*16 + mm] = e; sum += e;
        }
        sum += __shfl_xor_sync(0xffffffffu, sum, 1);
        sum += __shfl_xor_sync(0xffffffffu, sum, 2);
        if (q == 0) srinv[p] = 1.0f / sum;
    }
    __syncthreads();

    // ---- apply2 (hv shared over 2 p-rows) -> g_graph_in ----
    {
        int o4 = tid & 7, p0 = tid >> 3;
        const float* ap0 = &sB[p0*AST];
        const float* ap1 = &sB[(p0+32)*AST];
        const ulonglong2* hp2 = (const ulonglong2*)(sA + 2048);
        u64 a01_0 = 0ull, a23_0 = 0ull, a01_1 = 0ull, a23_1 = 0ull;
        #pragma unroll
        for (int m = 0; m < 64; m++) {
            ulonglong2 hv = hp2[m*8 + o4];
            u64 ad;
            PACK2(ad, ap0[m], ap0[m]); FMA2(a01_0, ad, hv.x); FMA2(a23_0, ad, hv.y);
            PACK2(ad, ap1[m], ap1[m]); FMA2(a01_1, ad, hv.x); FMA2(a23_1, ad, hv.y);
        }
        float4 bb = sb1v[o4];
        {
            float4 acc;
            UNPACK2(acc.x, acc.y, a01_0);
            UNPACK2(acc.z, acc.w, a23_0);
            float ri = srinv[p0];
            float4 res2;
            res2.x = acc.x*ri + bb.x; res2.y = acc.y*ri + bb.y;
            res2.z = acc.z*ri + bb.z; res2.w = acc.w*ri + bb.w;
            ((float4*)g_graph_in)[((size_t)tIdx*NN + sIdx*64 + p0)*8 + o4] = res2;
        }
        {
            float4 acc;
            UNPACK2(acc.x, acc.y, a01_1);
            UNPACK2(acc.z, acc.w, a23_1);
            float ri = srinv[p0 + 32];
            float4 res2;
            res2.x = acc.x*ri + bb.x; res2.y = acc.y*ri + bb.y;
            res2.z = acc.z*ri + bb.z; res2.w = acc.w*ri + bb.w;
            ((float4*)g_graph_in)[((size_t)tIdx*NN + sIdx*64 + p0 + 32)*8 + o4] = res2;
        }
    }
}

// ---------------------------------------------------------------------------
// LSTM graph (fused x+h): input 32, hidden 32. Warp = 8 peds (4 f32x2 pairs).
// At t=7 also writes encoded[n][32:64].
// ---------------------------------------------------------------------------
__global__ void lstm_graph_kernel(
        const float* __restrict__ h0, const float* __restrict__ c0,
        const float* __restrict__ Wih, const float* __restrict__ Whh,
        const float* __restrict__ bih, const float* __restrict__ bhh,
        float* __restrict__ hs, float* __restrict__ enc)
{
    __shared__ __align__(16) float4 sWih4[1024];  // [k][lane] -> gates
    __shared__ __align__(16) float4 sWhh4[1024];
    __shared__ __align__(16) float4 sb4[32];
    __shared__ __align__(16) u64 shx[1024];       // [w][k][pp]
    __shared__ __align__(16) u64 shh[1024];
    const int tid = threadIdx.x;

    for (int i = tid; i < 4096; i += 256) {
        int r = i >> 5, k = i & 31;
        int idx = (k*32 + (r & 31))*4 + (r >> 5);
        ((float*)sWih4)[idx] = Wih[i];
        ((float*)sWhh4)[idx] = Whh[i];
    }
    if (tid < 128) ((float*)sb4)[(tid & 31)*4 + (tid >> 5)] = bih[tid] + bhh[tid];
    __syncthreads();

    const int lane = tid & 31;
    const int w = tid >> 5;
    const int n0 = blockIdx.x * 64 + w * 8;

    float h[8], c[8];
    #pragma unroll
    for (int r = 0; r < 8; r++) { h[r] = h0[(n0+r)*32 + lane]; c[r] = c0[(n0+r)*32 + lane]; }

    const float4 bb = sb4[lane];
    u64 bd[4];
    PACK2(bd[0], bb.x, bb.x); PACK2(bd[1], bb.y, bb.y);
    PACK2(bd[2], bb.z, bb.z); PACK2(bd[3], bb.w, bb.w);

    #pragma unroll 1
    for (int t = 0; t < TT; t++) {
        __syncwarp();
        #pragma unroll
        for (int pr = 0; pr < 4; pr++) {
            float x0 = g_graph_in[((size_t)t*NN + n0 + 2*pr    )*32 + lane];
            float x1 = g_graph_in[((size_t)t*NN + n0 + 2*pr + 1)*32 + lane];
            u64 xq, hq;
            PACK2(xq, x0, x1);
            PACK2(hq, h[2*pr], h[2*pr+1]);
            shx[(w*32 + lane)*4 + pr] = xq;
            shh[(w*32 + lane)*4 + pr] = hq;
        }
        __syncwarp();

        u64 ac[16];   // [g*4 + pp]
        #pragma unroll
        for (int g = 0; g < 4; g++) {
            ac[g*4] = bd[g]; ac[g*4+1] = bd[g]; ac[g*4+2] = bd[g]; ac[g*4+3] = bd[g];
        }

        #pragma unroll
        for (int k = 0; k < 32; k++) {
            float4 wi = sWih4[k*32 + lane];
            float4 wh = sWhh4[k*32 + lane];
            ulonglong2 xa = *(const ulonglong2*)&shx[(w*32 + k)*4];
            ulonglong2 xb = *(const ulonglong2*)&shx[(w*32 + k)*4 + 2];
            ulonglong2 ha = *(const ulonglong2*)&shh[(w*32 + k)*4];
            ulonglong2 hb = *(const ulonglong2*)&shh[(w*32 + k)*4 + 2];
            u64 d;
            PACK2(d, wi.x, wi.x);
            FMA2(ac[0],  xa.x, d); FMA2(ac[1],  xa.y, d); FMA2(ac[2],  xb.x, d); FMA2(ac[3],  xb.y, d);
            PACK2(d, wi.y, wi.y);
            FMA2(ac[4],  xa.x, d); FMA2(ac[5],  xa.y, d); FMA2(ac[6],  xb.x, d); FMA2(ac[7],  xb.y, d);
            PACK2(d, wi.z, wi.z);
            FMA2(ac[8],  xa.x, d); FMA2(ac[9],  xa.y, d); FMA2(ac[10], xb.x, d); FMA2(ac[11], xb.y, d);
            PACK2(d, wi.w, wi.w);
            FMA2(ac[12], xa.x, d); FMA2(ac[13], xa.y, d); FMA2(ac[14], xb.x, d); FMA2(ac[15], xb.y, d);
            PACK2(d, wh.x, wh.x);
            FMA2(ac[0],  ha.x, d); FMA2(ac[1],  ha.y, d); FMA2(ac[2],  hb.x, d); FMA2(ac[3],  hb.y, d);
            PACK2(d, wh.y, wh.y);
            FMA2(ac[4],  ha.x, d); FMA2(ac[5],  ha.y, d); FMA2(ac[6],  hb.x, d); FMA2(ac[7],  hb.y, d);
            PACK2(d, wh.z, wh.z);
            FMA2(ac[8],  ha.x, d); FMA2(ac[9],  ha.y, d); FMA2(ac[10], hb.x, d); FMA2(ac[11], hb.y, d);
            PACK2(d, wh.w, wh.w);
            FMA2(ac[12], ha.x, d); FMA2(ac[13], ha.y, d); FMA2(ac[14], hb.x, d); FMA2(ac[15], hb.y, d);
        }

        #pragma unroll
        for (int pr = 0; pr < 4; pr++) {
            float A0a, A0b, A1a, A1b, A2a, A2b, A3a, A3b;
            UNPACK2(A0a, A0b, ac[0*4 + pr]);
            UNPACK2(A1a, A1b, ac[1*4 + pr]);
            UNPACK2(A2a, A2b, ac[2*4 + pr]);
            UNPACK2(A3a, A3b, ac[3*4 + pr]);
            int r0 = 2*pr, r1 = 2*pr + 1;
            c[r0] = sig_fast(A1a) * c[r0] + sig_fast(A0a) * tanh_fast(A2a);
            h[r0] = sig_fast(A3a) * tanh_fast(c[r0]);
            c[r1] = sig_fast(A1b) * c[r1] + sig_fast(A0b) * tanh_fast(A2b);
            h[r1] = sig_fast(A3b) * tanh_fast(c[r1]);
            hs[((size_t)t*NN + n0 + r0)*32 + lane] = h[r0];
            hs[((size_t)t*NN + n0 + r1)*32 + lane] = h[r1];
        }
        if (t == TT-1) {
            #pragma unroll
            for (int r = 0; r < 8; r++)
                enc[(size_t)(n0 + r)*72 + 32 + lane] = h[r];
        }
    }
}

// ---------------------------------------------------------------------------
// z-fill: encoded[n][64:72] = z[n/64]   (two float4 per ped)
// ---------------------------------------------------------------------------
__global__ void zfill_kernel(const float* __restrict__ z, float* __restrict__ out)
{
    int idx = blockIdx.x * blockDim.x + threadIdx.x;   // 0 .. NN*2-1
    if (idx >= NN*2) return;
    int n = idx >> 1, j = idx & 1;
    float4 v = ((const float4*)z)[(n >> 6)*2 + j];
    *(float4*)(out + (size_t)n*72 + 64 + j*4) = v;
}

extern "C" void kernel_launch(void* const* d_in, const int* in_sizes, int n_in,
                              void* d_out, int out_size) {
    const float* obs  = (const float*)d_in[0];
    const float* h0t  = (const float*)d_in[1];
    const float* c0t  = (const float*)d_in[2];
    const float* h0g  = (const float*)d_in[3];
    const float* c0g  = (const float*)d_in[4];
    const float* z    = (const float*)d_in[5];
    const float* WihT = (const float*)d_in[6];
    const float* WhhT = (const float*)d_in[7];
    const float* bihT = (const float*)d_in[8];
    const float* bhhT = (const float*)d_in[9];
    const float* WihG = (const float*)d_in[10];
    const float* WhhG = (const float*)d_in[11];
    const float* bihG = (const float*)d_in[12];
    const float* bhhG = (const float*)d_in[13];
    const float* w0   = (const float*)d_in[14];
    const float* as0  = (const float*)d_in[15];
    const float* ad0  = (const float*)d_in[16];
    const float* b0   = (const float*)d_in[17];
    const float* w1   = (const float*)d_in[18];
    const float* as1  = (const float*)d_in[19];
    const float* ad1  = (const float*)d_in[20];
    const float* b1   = (const float*)d_in[21];
    float* out = (float*)d_out;

    float* traj_hs;
    float* graph_hs;
    if (out_size >= ENC_ELEMS + 2*SEQ_ELEMS) {
        graph_hs = out + ENC_ELEMS;
        traj_hs  = out + ENC_ELEMS + SEQ_ELEMS;
    } else {
        void* pt = nullptr; void* pg = nullptr;
        cudaGetSymbolAddress(&pt, g_traj_fb);
        cudaGetSymbolAddress(&pg, g_graph_fb);
        traj_hs  = (float*)pt;
        graph_hs = (float*)pg;
    }

    lstm_traj_kernel<<<NN/64, 256>>>(obs, h0t, c0t, WihT, WhhT, bihT, bhhT, traj_hs, out);
    gat_fused_kernel<<<SS*TT, 256>>>(traj_hs, w0, as0, ad0, b0, w1, as1, ad1, b1);
    lstm_graph_kernel<<<NN/64, 256>>>(h0g, c0g, WihG, WhhG, bihG, bhhG, graph_hs, out);
    zfill_kernel<<<(NN*2 + 255)/256, 256>>>(z, out);
}

// round 17
// speedup vs baseline: 1.5115x; 1.0036x over previous
#include <cuda_runtime.h>
#include <math.h>

#define SS 512
#define PP 64
#define TT 8
#define NN (SS*PP)            // 32768

#define ENC_ELEMS (NN*72)     // 2359296
#define SEQ_ELEMS (TT*NN*32)  // 8388608

#define AST 68                // padded attention row stride (floats)

typedef unsigned long long u64;

__device__ float g_graph_in[SEQ_ELEMS];        // GAT output -> graph LSTM input
__device__ float g_traj_fb[SEQ_ELEMS];
__device__ float g_graph_fb[SEQ_ELEMS];

__device__ __forceinline__ float tanh_fast(float x){
    float y; asm("tanh.approx.f32 %0, %1;" : "=f"(y) : "f"(x)); return y;
}
__device__ __forceinline__ float sig_fast(float x){
    return 0.5f * tanh_fast(0.5f * x) + 0.5f;
}

#define FMA2(d, a, b) asm("fma.rn.f32x2 %0, %1, %2, %0;" : "+l"(d) : "l"(a), "l"(b))
#define PACK2(d, lo, hi) asm("mov.b64 %0, {%1, %2};" : "=l"(d) : "f"(lo), "f"(hi))
#define UNPACK2(lo, hi, s) asm("mov.b64 {%0, %1}, %2;" : "=f"(lo), "=f"(hi) : "l"(s))

// ---------------------------------------------------------------------------
// LSTM traj: input 3, hidden 32, T=8. Warp = 8 peds (4 f32x2 pairs).
// At t=7 writes encoded[n][0:32] and encoded[n][64:72] (z broadcast).
// ---------------------------------------------------------------------------
__global__ void lstm_traj_kernel(const float* __restrict__ x,
        const float* __restrict__ h0, const float* __restrict__ c0,
        const float* __restrict__ Wih, const float* __restrict__ Whh,
        const float* __restrict__ bih, const float* __restrict__ bhh,
        const float* __restrict__ z,
        float* __restrict__ hs, float* __restrict__ enc)
{
    __shared__ __align__(16) float4 sWhh4[1024];  // [k][lane] -> gates
    __shared__ __align__(16) float4 sWihP[96];    // [j=0..2][lane] -> gates
    __shared__ __align__(16) float4 sb4[32];
    __shared__ __align__(16) u64 shh[1024];       // [w][lane][pr]
    const int tid = threadIdx.x;

    for (int i = tid; i < 4096; i += 256) {
        int r = i >> 5, k = i & 31;
        ((float*)sWhh4)[(k*32 + (r & 31))*4 + (r >> 5)] = Whh[i];
    }
    for (int i = tid; i < 384; i += 256) {
        int r = i / 3, j = i - r*3;
        ((float*)sWihP)[(j*32 + (r & 31))*4 + (r >> 5)] = Wih[i];
    }
    if (tid < 128) ((float*)sb4)[(tid & 31)*4 + (tid >> 5)] = bih[tid] + bhh[tid];
    __syncthreads();

    const int lane = tid & 31;
    const int w = tid >> 5;
    const int n0 = blockIdx.x * 64 + w * 8;

    float h[8], c[8];
    #pragma unroll
    for (int r = 0; r < 8; r++) { h[r] = h0[(n0+r)*32 + lane]; c[r] = c0[(n0+r)*32 + lane]; }

    const float4 bb = sb4[lane];
    u64 bd[4];
    PACK2(bd[0], bb.x, bb.x); PACK2(bd[1], bb.y, bb.y);
    PACK2(bd[2], bb.z, bb.z); PACK2(bd[3], bb.w, bb.w);

    #pragma unroll 1
    for (int t = 0; t < TT; t++) {
        __syncwarp();
        #pragma unroll
        for (int pr = 0; pr < 4; pr++) {
            u64 hq;
            PACK2(hq, h[2*pr], h[2*pr+1]);
            shh[(w*32 + lane)*4 + pr] = hq;
        }
        __syncwarp();

        u64 ac[16];   // [g*4 + pp]
        #pragma unroll
        for (int g = 0; g < 4; g++) {
            ac[g*4] = bd[g]; ac[g*4+1] = bd[g]; ac[g*4+2] = bd[g]; ac[g*4+3] = bd[g];
        }

        const float* xp = x + ((size_t)t*NN + n0) * 3;
        #pragma unroll
        for (int j = 0; j < 3; j++) {
            float4 wj = sWihP[j*32 + lane];
            u64 xq[4];
            #pragma unroll
            for (int pr = 0; pr < 4; pr++)
                PACK2(xq[pr], xp[(2*pr)*3 + j], xp[(2*pr+1)*3 + j]);
            u64 d;
            PACK2(d, wj.x, wj.x);
            FMA2(ac[0],  xq[0], d); FMA2(ac[1],  xq[1], d); FMA2(ac[2],  xq[2], d); FMA2(ac[3],  xq[3], d);
            PACK2(d, wj.y, wj.y);
            FMA2(ac[4],  xq[0], d); FMA2(ac[5],  xq[1], d); FMA2(ac[6],  xq[2], d); FMA2(ac[7],  xq[3], d);
            PACK2(d, wj.z, wj.z);
            FMA2(ac[8],  xq[0], d); FMA2(ac[9],  xq[1], d); FMA2(ac[10], xq[2], d); FMA2(ac[11], xq[3], d);
            PACK2(d, wj.w, wj.w);
            FMA2(ac[12], xq[0], d); FMA2(ac[13], xq[1], d); FMA2(ac[14], xq[2], d); FMA2(ac[15], xq[3], d);
        }

        #pragma unroll
        for (int k = 0; k < 32; k++) {
            float4 wh = sWhh4[k*32 + lane];
            ulonglong2 ha = *(const ulonglong2*)&shh[(w*32 + k)*4];
            ulonglong2 hb = *(const ulonglong2*)&shh[(w*32 + k)*4 + 2];
            u64 d;
            PACK2(d, wh.x, wh.x);
            FMA2(ac[0],  ha.x, d); FMA2(ac[1],  ha.y, d); FMA2(ac[2],  hb.x, d); FMA2(ac[3],  hb.y, d);
            PACK2(d, wh.y, wh.y);
            FMA2(ac[4],  ha.x, d); FMA2(ac[5],  ha.y, d); FMA2(ac[6],  hb.x, d); FMA2(ac[7],  hb.y, d);
            PACK2(d, wh.z, wh.z);
            FMA2(ac[8],  ha.x, d); FMA2(ac[9],  ha.y, d); FMA2(ac[10], hb.x, d); FMA2(ac[11], hb.y, d);
            PACK2(d, wh.w, wh.w);
            FMA2(ac[12], ha.x, d); FMA2(ac[13], ha.y, d); FMA2(ac[14], hb.x, d); FMA2(ac[15], hb.y, d);
        }

        #pragma unroll
        for (int pr = 0; pr < 4; pr++) {
            float A0a, A0b, A1a, A1b, A2a, A2b, A3a, A3b;
            UNPACK2(A0a, A0b, ac[0*4 + pr]);
            UNPACK2(A1a, A1b, ac[1*4 + pr]);
            UNPACK2(A2a, A2b, ac[2*4 + pr]);
            UNPACK2(A3a, A3b, ac[3*4 + pr]);
            int r0 = 2*pr, r1 = 2*pr + 1;
            c[r0] = sig_fast(A1a) * c[r0] + sig_fast(A0a) * tanh_fast(A2a);
            h[r0] = sig_fast(A3a) * tanh_fast(c[r0]);
            c[r1] = sig_fast(A1b) * c[r1] + sig_fast(A0b) * tanh_fast(A2b);
            h[r1] = sig_fast(A3b) * tanh_fast(c[r1]);
            hs[((size_t)t*NN + n0 + r0)*32 + lane] = h[r0];
            hs[((size_t)t*NN + n0 + r1)*32 + lane] = h[r1];
        }
        if (t == TT-1) {
            #pragma unroll
            for (int r = 0; r < 8; r++)
                enc[(size_t)(n0 + r)*72 + lane] = h[r];
            if (lane < 8) {
                float zv = z[(n0 >> 6)*8 + lane];   // all 8 peds share scene
                #pragma unroll
                for (int r = 0; r < 8; r++)
                    enc[(size_t)(n0 + r)*72 + 64 + lane] = zv;
            }
        }
    }
}

// ---------------------------------------------------------------------------
// FUSED GAT: layer0 (4 heads) + layer1. __launch_bounds__ for occupancy.
// ---------------------------------------------------------------------------
__global__ void __launch_bounds__(256, 4) gat_fused_kernel(const float* __restrict__ traj,
        const float* __restrict__ w0, const float* __restrict__ as0,
        const float* __restrict__ ad0, const float* __restrict__ b0,
        const float* __restrict__ w1, const float* __restrict__ as1,
        const float* __restrict__ ad1, const float* __restrict__ b1)
{
    __shared__ __align__(16) float sA[4416];
    __shared__ __align__(16) float sB[4416];
    __shared__ float sS[256], sD[256];
    __shared__ __align__(16) float smean[64], sinv[64];
    __shared__ float srinv[64];
    __shared__ float sas0[64], sad0[64], sas1[32], sad1[32];
    __shared__ __align__(16) float4 sb0v[4];
    __shared__ __align__(16) float4 sb1v[8];

    const int tid = threadIdx.x;
    const int b = blockIdx.x, sIdx = b >> 3, tIdx = b & 7;

    float4* sxA = (float4*)sA;            // x quads [0:512)
    float4* swA = (float4*)(sA + 2048);   // w0 quads
    float4* hpB = (float4*)sB;            // hp0 / x2 quads

    // ---- prologue ----
    {
        const float4* src = (const float4*)(traj + ((size_t)tIdx*NN + sIdx*64) * 32);
        for (int i = tid; i < 512; i += 256) sxA[i] = src[i];
        const float4* wsrc = (const float4*)w0;
        for (int i = tid; i < 512; i += 256) swA[i] = wsrc[i];
        if (tid < 64) { sas0[tid] = as0[tid]; sad0[tid] = ad0[tid]; }
        if (tid < 32) { sas1[tid] = as1[tid]; sad1[tid] = ad1[tid]; }
        if (tid < 4)  sb0v[tid] = ((const float4*)b0)[tid];
        if (tid < 8)  sb1v[tid] = ((const float4*)b1)[tid];
    }
    __syncthreads();

    // ---- layer0 instance-norm stats ----
    {
        int f = tid & 31, g = tid >> 5;
        float s = 0.f, s2 = 0.f;
        #pragma unroll
        for (int i = 0; i < 8; i++) { float v = sA[(g*8+i)*32 + f]; s += v; s2 += v*v; }
        sB[g*32 + f] = s;
        sB[256 + g*32 + f] = s2;
    }
    __syncthreads();
    if (tid < 32) {
        float s = 0.f, s2 = 0.f;
        #pragma unroll
        for (int g = 0; g < 8; g++) { s += sB[g*32 + tid]; s2 += sB[256 + g*32 + tid]; }
        float m = s * (1.0f/64.0f);
        float var = s2 * (1.0f/64.0f) - m*m;
        smean[tid] = m; sinv[tid] = rsqrtf(var + 1e-5f);
    }
    __syncthreads();
    for (int i = tid; i < 512; i += 256) {
        int f4 = i & 7;
        float4 m4 = ((float4*)smean)[f4], i4 = ((float4*)sinv)[f4];
        float4 v = sxA[i];
        v.x = (v.x - m4.x)*i4.x; v.y = (v.y - m4.y)*i4.y;
        v.z = (v.z - m4.z)*i4.z; v.w = (v.w - m4.w)*i4.w;
        sxA[i] = v;
    }
    __syncthreads();

    // ---- hp0 matmul (FMA2, weights shared over 4 p-rows per thread) ----
    {
        int j = tid & 15, hh = j >> 2, o4 = j & 3;
        int p0 = tid >> 4;
        u64 a01[4] = {0,0,0,0}, a23[4] = {0,0,0,0};
        #pragma unroll
        for (int f4 = 0; f4 < 8; f4++) {
            const ulonglong2* wp = (const ulonglong2*)&swA[hh*128 + (f4*4)*4 + o4];
            ulonglong2 wv0 = wp[0], wv1 = wp[4], wv2 = wp[8], wv3 = wp[12];
            #pragma unroll
            for (int r = 0; r < 4; r++) {
                float4 xv = sxA[(p0 + r*16)*8 + f4];
                u64 xd;
                PACK2(xd, xv.x, xv.x); FMA2(a01[r], xd, wv0.x); FMA2(a23[r], xd, wv0.y);
                PACK2(xd, xv.y, xv.y); FMA2(a01[r], xd, wv1.x); FMA2(a23[r], xd, wv1.y);
                PACK2(xd, xv.z, xv.z); FMA2(a01[r], xd, wv2.x); FMA2(a23[r], xd, wv2.y);
                PACK2(xd, xv.w, xv.w); FMA2(a01[r], xd, wv3.x); FMA2(a23[r], xd, wv3.y);
            }
        }
        #pragma unroll
        for (int r = 0; r < 4; r++) {
            u64* dst = (u64*)sB + ((p0 + r*16)*16 + hh*4 + o4)*2;
            dst[0] = a01[r]; dst[1] = a23[r];
        }
    }
    __syncthreads();

    // ---- s[h][p], d[h][p] ----
    {
        int hh = tid >> 6, p = tid & 63;
        float as = 0.f, ad = 0.f;
        #pragma unroll
        for (int o4 = 0; o4 < 4; o4++) {
            float4 v = hpB[p*16 + hh*4 + o4];
            int ob = hh*16 + o4*4;
            as += v.x*sas0[ob] + v.y*sas0[ob+1] + v.z*sas0[ob+2] + v.w*sas0[ob+3];
            ad += v.x*sad0[ob] + v.y*sad0[ob+1] + v.z*sad0[ob+2] + v.w*sad0[ob+3];
        }
        sS[tid] = as; sD[tid] = ad;
    }
    __syncthreads();

    // ---- heads loop (immediate x2 write, minimal live regs) ----
    for (int hh = 0; hh < 4; hh++) {
        {
            int p = tid >> 2, q = tid & 3;
            float sp = sS[hh*64 + p];
            float l[16]; float mx = -1e30f;
            #pragma unroll
            for (int mm = 0; mm < 16; mm++) {
                float v = sp + sD[hh*64 + q*16 + mm];
                v = (v > 0.f) ? v : 0.2f*v;
                l[mm] = v; mx = fmaxf(mx, v);
            }
            mx = fmaxf(mx, __shfl_xor_sync(0xffffffffu, mx, 1));
            mx = fmaxf(mx, __shfl_xor_sync(0xffffffffu, mx, 2));
            float sum = 0.f;
            #pragma unroll
            for (int mm = 0; mm < 16; mm++) {
                float e = __expf(l[mm] - mx);
                sA[p*AST + q*16 + mm] = e; sum += e;
            }
            sum += __shfl_xor_sync(0xffffffffu, sum, 1);
            sum += __shfl_xor_sync(0xffffffffu, sum, 2);
            if (q == 0) srinv[p] = 1.0f / sum;
        }
        __syncthreads();
        float4 res;
        {
            int p = tid >> 2, o4 = tid & 3;
            const float* ap = &sA[p*AST];
            const ulonglong2* hp2 = (const ulonglong2*)sB;
            u64 a01 = 0ull, a23 = 0ull;
            #pragma unroll
            for (int m = 0; m < 64; m++) {
                u64 ad; PACK2(ad, ap[m], ap[m]);
                ulonglong2 hv = hp2[m*16 + hh*4 + o4];
                FMA2(a01, ad, hv.x); FMA2(a23, ad, hv.y);
            }
            float4 acc;
            UNPACK2(acc.x, acc.y, a01);
            UNPACK2(acc.z, acc.w, a23);
            float ri = srinv[p];
            float4 bb = sb0v[o4];
            res.x = acc.x*ri + bb.x; res.y = acc.y*ri + bb.y;
            res.z = acc.z*ri + bb.z; res.w = acc.w*ri + bb.w;
            res.x = (res.x > 0.f) ? res.x : (__expf(res.x) - 1.f);
            res.y = (res.y > 0.f) ? res.y : (__expf(res.y) - 1.f);
            res.z = (res.z > 0.f) ? res.z : (__expf(res.z) - 1.f);
            res.w = (res.w > 0.f) ? res.w : (__expf(res.w) - 1.f);
        }
        __syncthreads();   // hp reads (this head's region) done
        {
            int p = tid >> 2, o4 = tid & 3;
            hpB[p*16 + hh*4 + o4] = res;
        }
        __syncthreads();
    }
    // sB now holds x2[64][64]

    // ---- layer1 instance-norm stats ----
    {
        int f = tid & 63, g = tid >> 6;
        float s = 0.f, s2 = 0.f;
        #pragma unroll
        for (int i = 0; i < 16; i++) { float v = sB[(g*16+i)*64 + f]; s += v; s2 += v*v; }
        sA[g*64 + f] = s;
        sA[256 + g*64 + f] = s2;
    }
    __syncthreads();
    if (tid < 64) {
        float s = 0.f, s2 = 0.f;
        #pragma unroll
        for (int g = 0; g < 4; g++) { s += sA[g*64 + tid]; s2 += sA[256 + g*64 + tid]; }
        float m = s * (1.0f/64.0f);
        float var = s2 * (1.0f/64.0f) - m*m;
        smean[tid] = m; sinv[tid] = rsqrtf(var + 1e-5f);
    }
    __syncthreads();
    for (int i = tid; i < 1024; i += 256) {
        int f4 = i & 15;
        float4 m4 = ((float4*)smean)[f4], i4 = ((float4*)sinv)[f4];
        float4 v = hpB[i];
        v.x = (v.x - m4.x)*i4.x; v.y = (v.y - m4.y)*i4.y;
        v.z = (v.z - m4.z)*i4.z; v.w = (v.w - m4.w)*i4.w;
        hpB[i] = v;
    }
    for (int i = tid; i < 512; i += 256) ((float4*)sA)[i] = ((const float4*)w1)[i];
    __syncthreads();

    // ---- hp1 matmul (FMA2, weights shared over 2 p-rows) ----
    {
        float4* sw1q = (float4*)sA;
        int o4 = tid & 7, p0 = tid >> 3;
        u64 a01[2] = {0,0}, a23[2] = {0,0};
        #pragma unroll
        for (int f4 = 0; f4 < 16; f4++) {
            const ulonglong2* wp = (const ulonglong2*)&sw1q[(f4*4)*8 + o4];
            ulonglong2 wv0 = wp[0], wv1 = wp[8], wv2 = wp[16], wv3 = wp[24];
            #pragma unroll
            for (int r = 0; r < 2; r++) {
                float4 xv = hpB[(p0 + r*32)*16 + f4];
                u64 xd;
                PACK2(xd, xv.x, xv.x); FMA2(a01[r], xd, wv0.x); FMA2(a23[r], xd, wv0.y);
                PACK2(xd, xv.y, xv.y); FMA2(a01[r], xd, wv1.x); FMA2(a23[r], xd, wv1.y);
                PACK2(xd, xv.z, xv.z); FMA2(a01[r], xd, wv2.x); FMA2(a23[r], xd, wv2.y);
                PACK2(xd, xv.w, xv.w); FMA2(a01[r], xd, wv3.x); FMA2(a23[r], xd, wv3.y);
            }
        }
        #pragma unroll
        for (int r = 0; r < 2; r++) {
            u64* dst = (u64*)(sA + 2048) + ((p0 + r*32)*8 + o4)*2;
            dst[0] = a01[r]; dst[1] = a23[r];
        }
    }
    __syncthreads();

    // ---- s1/d1 ----
    if (tid < 64) {
        int p = tid;
        const float4* hp4 = (const float4*)(sA + 2048);
        float as = 0.f, ad = 0.f;
        #pragma unroll
        for (int o4 = 0; o4 < 8; o4++) {
            float4 v = hp4[p*8 + o4];
            as += v.x*sas1[o4*4] + v.y*sas1[o4*4+1] + v.z*sas1[o4*4+2] + v.w*sas1[o4*4+3];
            ad += v.x*sad1[o4*4] + v.y*sad1[o4*4+1] + v.z*sad1[o4*4+2] + v.w*sad1[o4*4+3];
        }
        sS[p] = as; sD[p] = ad;
    }
    __syncthreads();

    // ---- softmax2 into sB ----
    {
        int p = tid >> 2, q = tid & 3;
        float sp = sS[p];
        float l[16]; float mx = -1e30f;
        #pragma unroll
        for (int mm = 0; mm < 16; mm++) {
            float v = sp + sD[q*16 + mm];
            v = (v > 0.f) ? v : 0.2f*v;
            l[mm] = v; mx = fmaxf(mx, v);
        }
        mx = fmaxf(mx, __shfl_xor_sync(0xffffffffu, mx, 1));
        mx = fmaxf(mx, __shfl_xor_sync(0xffffffffu, mx, 2));
        float sum = 0.f;
        #pragma unroll
        for (int mm = 0; mm < 16; mm++) {
            float e = __expf(l[mm] - mx);
            sB[p*AST + q*16 + mm] = e; sum += e;
        }
        sum += __shfl_xor_sync(0xffffffffu, sum, 1);
        sum += __shfl_xor_sync(0xffffffffu, sum, 2);
        if (q == 0) srinv[p] = 1.0f / sum;
    }
    __syncthreads();

    // ---- apply2 (hv shared over 2 p-rows) -> g_graph_in ----
    {
        int o4 = tid & 7, p0 = tid >> 3;
        const float* ap0 = &sB[p0*AST];
        const float* ap1 = &sB[(p0+32)*AST];
        const ulonglong2* hp2 = (const ulonglong2*)(sA + 2048);
        u64 a01_0 = 0ull, a23_0 = 0ull, a01_1 = 0ull, a23_1 = 0ull;
        #pragma unroll
        for (int m = 0; m < 64; m++) {
            ulonglong2 hv = hp2[m*8 + o4];
            u64 ad;
            PACK2(ad, ap0[m], ap0[m]); FMA2(a01_0, ad, hv.x); FMA2(a23_0, ad, hv.y);
            PACK2(ad, ap1[m], ap1[m]); FMA2(a01_1, ad, hv.x); FMA2(a23_1, ad, hv.y);
        }
        float4 bb = sb1v[o4];
        {
            float4 acc;
            UNPACK2(acc.x, acc.y, a01_0);
            UNPACK2(acc.z, acc.w, a23_0);
            float ri = srinv[p0];
            float4 res2;
            res2.x = acc.x*ri + bb.x; res2.y = acc.y*ri + bb.y;
            res2.z = acc.z*ri + bb.z; res2.w = acc.w*ri + bb.w;
            ((float4*)g_graph_in)[((size_t)tIdx*NN + sIdx*64 + p0)*8 + o4] = res2;
        }
        {
            float4 acc;
            UNPACK2(acc.x, acc.y, a01_1);
            UNPACK2(acc.z, acc.w, a23_1);
            float ri = srinv[p0 + 32];
            float4 res2;
            res2.x = acc.x*ri + bb.x; res2.y = acc.y*ri + bb.y;
            res2.z = acc.z*ri + bb.z; res2.w = acc.w*ri + bb.w;
            ((float4*)g_graph_in)[((size_t)tIdx*NN + sIdx*64 + p0 + 32)*8 + o4] = res2;
        }
    }
}

// ---------------------------------------------------------------------------
// LSTM graph (fused x+h): input 32, hidden 32. Warp = 8 peds (4 f32x2 pairs).
// At t=7 also writes encoded[n][32:64].
// ---------------------------------------------------------------------------
__global__ void lstm_graph_kernel(
        const float* __restrict__ h0, const float* __restrict__ c0,
        const float* __restrict__ Wih, const float* __restrict__ Whh,
        const float* __restrict__ bih, const float* __restrict__ bhh,
        float* __restrict__ hs, float* __restrict__ enc)
{
    __shared__ __align__(16) float4 sWih4[1024];  // [k][lane] -> gates
    __shared__ __align__(16) float4 sWhh4[1024];
    __shared__ __align__(16) float4 sb4[32];
    __shared__ __align__(16) u64 shx[1024];       // [w][k][pp]
    __shared__ __align__(16) u64 shh[1024];
    const int tid = threadIdx.x;

    for (int i = tid; i < 4096; i += 256) {
        int r = i >> 5, k = i & 31;
        int idx = (k*32 + (r & 31))*4 + (r >> 5);
        ((float*)sWih4)[idx] = Wih[i];
        ((float*)sWhh4)[idx] = Whh[i];
    }
    if (tid < 128) ((float*)sb4)[(tid & 31)*4 + (tid >> 5)] = bih[tid] + bhh[tid];
    __syncthreads();

    const int lane = tid & 31;
    const int w = tid >> 5;
    const int n0 = blockIdx.x * 64 + w * 8;

    float h[8], c[8];
    #pragma unroll
    for (int r = 0; r < 8; r++) { h[r] = h0[(n0+r)*32 + lane]; c[r] = c0[(n0+r)*32 + lane]; }

    const float4 bb = sb4[lane];
    u64 bd[4];
    PACK2(bd[0], bb.x, bb.x); PACK2(bd[1], bb.y, bb.y);
    PACK2(bd[2], bb.z, bb.z); PACK2(bd[3], bb.w, bb.w);

    #pragma unroll 1
    for (int t = 0; t < TT; t++) {
        __syncwarp();
        #pragma unroll
        for (int pr = 0; pr < 4; pr++) {
            float x0 = g_graph_in[((size_t)t*NN + n0 + 2*pr    )*32 + lane];
            float x1 = g_graph_in[((size_t)t*NN + n0 + 2*pr + 1)*32 + lane];
            u64 xq, hq;
            PACK2(xq, x0, x1);
            PACK2(hq, h[2*pr], h[2*pr+1]);
            shx[(w*32 + lane)*4 + pr] = xq;
            shh[(w*32 + lane)*4 + pr] = hq;
        }
        __syncwarp();

        u64 ac[16];   // [g*4 + pp]
        #pragma unroll
        for (int g = 0; g < 4; g++) {
            ac[g*4] = bd[g]; ac[g*4+1] = bd[g]; ac[g*4+2] = bd[g]; ac[g*4+3] = bd[g];
        }

        #pragma unroll
        for (int k = 0; k < 32; k++) {
            float4 wi = sWih4[k*32 + lane];
            float4 wh = sWhh4[k*32 + lane];
            ulonglong2 xa = *(const ulonglong2*)&shx[(w*32 + k)*4];
            ulonglong2 xb = *(const ulonglong2*)&shx[(w*32 + k)*4 + 2];
            ulonglong2 ha = *(const ulonglong2*)&shh[(w*32 + k)*4];
            ulonglong2 hb = *(const ulonglong2*)&shh[(w*32 + k)*4 + 2];
            u64 d;
            PACK2(d, wi.x, wi.x);
            FMA2(ac[0],  xa.x, d); FMA2(ac[1],  xa.y, d); FMA2(ac[2],  xb.x, d); FMA2(ac[3],  xb.y, d);
            PACK2(d, wi.y, wi.y);
            FMA2(ac[4],  xa.x, d); FMA2(ac[5],  xa.y, d); FMA2(ac[6],  xb.x, d); FMA2(ac[7],  xb.y, d);
            PACK2(d, wi.z, wi.z);
            FMA2(ac[8],  xa.x, d); FMA2(ac[9],  xa.y, d); FMA2(ac[10], xb.x, d); FMA2(ac[11], xb.y, d);
            PACK2(d, wi.w, wi.w);
            FMA2(ac[12], xa.x, d); FMA2(ac[13], xa.y, d); FMA2(ac[14], xb.x, d); FMA2(ac[15], xb.y, d);
            PACK2(d, wh.x, wh.x);
            FMA2(ac[0],  ha.x, d); FMA2(ac[1],  ha.y, d); FMA2(ac[2],  hb.x, d); FMA2(ac[3],  hb.y, d);
            PACK2(d, wh.y, wh.y);
            FMA2(ac[4],  ha.x, d); FMA2(ac[5],  ha.y, d); FMA2(ac[6],  hb.x, d); FMA2(ac[7],  hb.y, d);
            PACK2(d, wh.z, wh.z);
            FMA2(ac[8],  ha.x, d); FMA2(ac[9],  ha.y, d); FMA2(ac[10], hb.x, d); FMA2(ac[11], hb.y, d);
            PACK2(d, wh.w, wh.w);
            FMA2(ac[12], ha.x, d); FMA2(ac[13], ha.y, d); FMA2(ac[14], hb.x, d); FMA2(ac[15], hb.y, d);
        }

        #pragma unroll
        for (int pr = 0; pr < 4; pr++) {
            float A0a, A0b, A1a, A1b, A2a, A2b, A3a, A3b;
            UNPACK2(A0a, A0b, ac[0*4 + pr]);
            UNPACK2(A1a, A1b, ac[1*4 + pr]);
            UNPACK2(A2a, A2b, ac[2*4 + pr]);
            UNPACK2(A3a, A3b, ac[3*4 + pr]);
            int r0 = 2*pr, r1 = 2*pr + 1;
            c[r0] = sig_fast(A1a) * c[r0] + sig_fast(A0a) * tanh_fast(A2a);
            h[r0] = sig_fast(A3a) * tanh_fast(c[r0]);
            c[r1] = sig_fast(A1b) * c[r1] + sig_fast(A0b) * tanh_fast(A2b);
            h[r1] = sig_fast(A3b) * tanh_fast(c[r1]);
            hs[((size_t)t*NN + n0 + r0)*32 + lane] = h[r0];
            hs[((size_t)t*NN + n0 + r1)*32 + lane] = h[r1];
        }
        if (t == TT-1) {
            #pragma unroll
            for (int r = 0; r < 8; r++)
                enc[(size_t)(n0 + r)*72 + 32 + lane] = h[r];
        }
    }
}

extern "C" void kernel_launch(void* const* d_in, const int* in_sizes, int n_in,
                              void* d_out, int out_size) {
    const float* obs  = (const float*)d_in[0];
    const float* h0t  = (const float*)d_in[1];
    const float* c0t  = (const float*)d_in[2];
    const float* h0g  = (const float*)d_in[3];
    const float* c0g  = (const float*)d_in[4];
    const float* z    = (const float*)d_in[5];
    const float* WihT = (const float*)d_in[6];
    const float* WhhT = (const float*)d_in[7];
    const float* bihT = (const float*)d_in[8];
    const float* bhhT = (const float*)d_in[9];
    const float* WihG = (const float*)d_in[10];
    const float* WhhG = (const float*)d_in[11];
    const float* bihG = (const float*)d_in[12];
    const float* bhhG = (const float*)d_in[13];
    const float* w0   = (const float*)d_in[14];
    const float* as0  = (const float*)d_in[15];
    const float* ad0  = (const float*)d_in[16];
    const float* b0   = (const float*)d_in[17];
    const float* w1   = (const float*)d_in[18];
    const float* as1  = (const float*)d_in[19];
    const float* ad1  = (const float*)d_in[20];
    const float* b1   = (const float*)d_in[21];
    float* out = (float*)d_out;

    float* traj_hs;
    float* graph_hs;
    if (out_size >= ENC_ELEMS + 2*SEQ_ELEMS) {
        graph_hs = out + ENC_ELEMS;
        traj_hs  = out + ENC_ELEMS + SEQ_ELEMS;
    } else {
        void* pt = nullptr; void* pg = nullptr;
        cudaGetSymbolAddress(&pt, g_traj_fb);
        cudaGetSymbolAddress(&pg, g_graph_fb);
        traj_hs  = (float*)pt;
        graph_hs = (float*)pg;
    }

    lstm_traj_kernel<<<NN/64, 256>>>(obs, h0t, c0t, WihT, WhhT, bihT, bhhT, z, traj_hs, out);
    gat_fused_kernel<<<SS*TT, 256>>>(traj_hs, w0, as0, ad0, b0, w1, as1, ad1, b1);
    lstm_graph_kernel<<<NN/64, 256>>>(h0g, c0g, WihG, WhhG, bihG, bhhG, graph_hs, out);
}